// round 15
// baseline (speedup 1.0000x reference)
#include <cuda_runtime.h>
#include <cuda_bf16.h>

#define K_B 2
#define K_R 5
#define K_N 1024
#define K_E 3
#define K_F 64
#define K_INRET 320
#define K_INTER 256
#define K_OUTRET 256
#define K_H1 128
#define K_HRET 320
#define K_CAT 384
#define INV_GAMMA 0.4f
#define SKH 12
#define SBN 72
#define NN1 (K_N * K_N)
#define NF1 (K_N * K_F)
#define PHALF (2 * K_N * K_OUTRET)
#define AS64 (64 * SKH)
#define AS128 (128 * SKH)
#define BSNN (8 * SBN)

// pre-split weight buffer offsets (uint pairs)
#define OFF_FC 0
#define LEN_FC (2 * 5 * 64 * 32)
#define OFF_Q  (OFF_FC + LEN_FC)
#define LEN_QKV (2 * 256 * 160)
#define OFF_K  (OFF_Q + LEN_QKV)
#define OFF_V  (OFF_K + LEN_QKV)
#define OFF_R  (OFF_V + LEN_QKV)
#define LEN_R  (2 * 256 * 128)
#define OFF_L1 (OFF_R + LEN_R)
#define LEN_L1 (2 * 128 * 160)
#define OFF_L2 (OFF_L1 + LEN_L1)
#define LEN_L2 (2 * 320 * 192)
#define OFF_M1 (OFF_L2 + LEN_L2)
#define LEN_M1 (128 * 160)
#define WTOT   (OFF_M1 + LEN_M1)

// ---------------- device scratch ----------------
__device__ __align__(16) float g_P[2 * K_B * K_R * K_N * K_F];
__device__ __align__(16) float g_diff [K_B * K_R * K_N * K_F];
__device__ __align__(16) float g_h    [K_B * K_R * K_N * K_F];
__device__ __align__(16) float g_v [K_B * K_N * K_INTER];
__device__ __align__(16) float g_ms[K_B * K_N * K_N];
__device__ __align__(16) float g_cat[K_B * K_N * K_CAT];
__device__ __align__(16) float g_skipA[K_B * K_N * K_HRET];
__device__ __align__(16) float g_skipB[K_B * K_N * K_HRET];
__device__ __align__(16) float g_m1[K_B * K_N * K_H1];
__device__ __align__(16) unsigned g_Wh[WTOT];
__device__ __align__(16) unsigned g_Wl[WTOT];
__device__ __align__(16) unsigned g_qh[K_B * K_N * 128];
__device__ __align__(16) unsigned g_ql[K_B * K_N * 128];
__device__ __align__(16) unsigned g_kh[K_B * K_N * 128];
__device__ __align__(16) unsigned g_kl[K_B * K_N * 128];

// ---------------- bf16 split helpers ----------------
__device__ __forceinline__ unsigned as_u(__nv_bfloat162 v) {
    return reinterpret_cast<unsigned&>(v);
}
__device__ __forceinline__ void bsplit4(float4 v, uint2& hi, uint2& lo) {
    __nv_bfloat162 h01 = __floats2bfloat162_rn(v.x, v.y);
    __nv_bfloat162 h23 = __floats2bfloat162_rn(v.z, v.w);
    float r0 = v.x - __bfloat162float(h01.x);
    float r1 = v.y - __bfloat162float(h01.y);
    float r2 = v.z - __bfloat162float(h23.x);
    float r3 = v.w - __bfloat162float(h23.y);
    __nv_bfloat162 l01 = __floats2bfloat162_rn(r0, r1);
    __nv_bfloat162 l23 = __floats2bfloat162_rn(r2, r3);
    hi = make_uint2(as_u(h01), as_u(h23));
    lo = make_uint2(as_u(l01), as_u(l23));
}
__device__ __forceinline__ void bsplit2(float a, float b, unsigned& hi, unsigned& lo) {
    __nv_bfloat162 h = __floats2bfloat162_rn(a, b);
    float ra = a - __bfloat162float(h.x);
    float rb = b - __bfloat162float(h.y);
    __nv_bfloat162 l = __floats2bfloat162_rn(ra, rb);
    hi = as_u(h); lo = as_u(l);
}

__device__ __forceinline__ void mmabf(float acc[4], const unsigned a[4], const unsigned b[2]) {
    asm volatile(
        "mma.sync.aligned.m16n8k16.row.col.f32.bf16.bf16.f32 "
        "{%0,%1,%2,%3}, {%4,%5,%6,%7}, {%8,%9}, {%0,%1,%2,%3};"
        : "+f"(acc[0]), "+f"(acc[1]), "+f"(acc[2]), "+f"(acc[3])
        : "r"(a[0]), "r"(a[1]), "r"(a[2]), "r"(a[3]), "r"(b[0]), "r"(b[1]));
}

__device__ __forceinline__ void lda_bf(const unsigned* A, int mrow, int g, int q,
                                       unsigned a[4]) {
    const unsigned* p = &A[(mrow + g) * SKH + q];
    a[0] = p[0];
    a[1] = p[8 * SKH];
    a[2] = p[4];
    a[3] = p[8 * SKH + 4];
}
__device__ __forceinline__ void ldb_nt(const unsigned* B, int nrow, int g, int q,
                                       unsigned b[2]) {
    const unsigned* p = &B[(nrow + g) * SKH + q];
    b[0] = p[0]; b[1] = p[4];
}
__device__ __forceinline__ void ldb_nn(const unsigned* B, int ncol, int g, int q,
                                       unsigned b[2]) {
    b[0] = B[q * SBN + ncol + g];
    b[1] = B[(q + 4) * SBN + ncol + g];
}

template<bool BNN>
__device__ __forceinline__ void warp_bmma(const unsigned* Ah, const unsigned* Al,
                                          const unsigned* Bh, const unsigned* Bl,
                                          int mw, int nw, int g, int q, float acc[4][4]) {
    unsigned ah[4], al[4];
    lda_bf(Ah, mw, g, q, ah);
    lda_bf(Al, mw, g, q, al);
#pragma unroll
    for (int j = 0; j < 4; j++) {
        unsigned bh[2], bl[2];
        if (BNN) { ldb_nn(Bh, nw + 8 * j, g, q, bh); ldb_nn(Bl, nw + 8 * j, g, q, bl); }
        else     { ldb_nt(Bh, nw + 8 * j, g, q, bh); ldb_nt(Bl, nw + 8 * j, g, q, bl); }
        mmabf(acc[j], ah, bh);
        mmabf(acc[j], ah, bl);
        mmabf(acc[j], al, bh);
    }
}

__device__ __forceinline__ void warp_bmma128(const unsigned* Ah, const unsigned* Al,
                                             const unsigned* Bh, const unsigned* Bl,
                                             int mw, int nw, int g, int q,
                                             float acc[2][4][4]) {
    unsigned ah0[4], al0[4], ah1[4], al1[4];
    lda_bf(Ah, mw, g, q, ah0);
    lda_bf(Al, mw, g, q, al0);
    lda_bf(Ah, mw + 64, g, q, ah1);
    lda_bf(Al, mw + 64, g, q, al1);
#pragma unroll
    for (int j = 0; j < 4; j++) {
        unsigned bh[2], bl[2];
        ldb_nt(Bh, nw + 8 * j, g, q, bh);
        ldb_nt(Bl, nw + 8 * j, g, q, bl);
        mmabf(acc[0][j], ah0, bh); mmabf(acc[0][j], ah0, bl); mmabf(acc[0][j], al0, bh);
        mmabf(acc[1][j], ah1, bh); mmabf(acc[1][j], ah1, bl); mmabf(acc[1][j], al1, bh);
    }
}

// ---------------- loops (all NEW global loads are SCALAR 32-bit) ----------------
template<bool ADD2>
__device__ __forceinline__ void loop64_nt_pb(const float* __restrict__ Az,
                                             const float* __restrict__ A2z, int ldA,
                                             const unsigned* __restrict__ Bhg,
                                             const unsigned* __restrict__ Blg, int ldBp,
                                             int K, unsigned* Ah, unsigned* Al,
                                             unsigned* Bh, unsigned* Bl, float acc[4][4]) {
    int tid = threadIdx.x;
    int r_ = tid >> 2, q_ = tid & 3;
    int lane = tid & 31, g = lane >> 2, q = lane & 3;
    int warp = tid >> 5, mw = (warp & 3) * 16, nw = (warp >> 2) * 32;
    int aoff = r_ * SKH + q_ * 2;
    long bbase = (long)r_ * ldBp + q_ * 2;
    float4 ar = *(const float4*)&Az[(long)r_ * ldA + q_ * 4];
    unsigned bh0 = Bhg[bbase], bh1 = Bhg[bbase + 1];
    unsigned bl0 = Blg[bbase], bl1 = Blg[bbase + 1];
    float4 a2 = make_float4(0.f, 0.f, 0.f, 0.f);
    if (ADD2) a2 = *(const float4*)&A2z[(long)r_ * ldA + q_ * 4];
    for (int k0 = 0; k0 < K; k0 += 16) {
        if (ADD2) { ar.x += a2.x; ar.y += a2.y; ar.z += a2.z; ar.w += a2.w; }
        uint2 h, l;
        bsplit4(ar, h, l);
        *(uint2*)&Ah[aoff] = h; *(uint2*)&Al[aoff] = l;
        *(uint2*)&Bh[aoff] = make_uint2(bh0, bh1);
        *(uint2*)&Bl[aoff] = make_uint2(bl0, bl1);
        __syncthreads();
        int kn = k0 + 16;
        if (kn < K) {
            ar = *(const float4*)&Az[(long)r_ * ldA + kn + q_ * 4];
            long bo = bbase + kn / 2;
            bh0 = Bhg[bo]; bh1 = Bhg[bo + 1];
            bl0 = Blg[bo]; bl1 = Blg[bo + 1];
            if (ADD2) a2 = *(const float4*)&A2z[(long)r_ * ldA + kn + q_ * 4];
        }
        warp_bmma<false>(Ah, Al, Bh, Bl, mw, nw, g, q, acc);
        __syncthreads();
    }
}

// NN (feats/ret): unchanged R9.
__device__ __forceinline__ void loop64_nn(const float* __restrict__ Az, int ldA,
                                          const float* __restrict__ Bz, int ldB, int K,
                                          unsigned* Ah, unsigned* Al,
                                          unsigned* Bh, unsigned* Bl, float acc[4][4]) {
    int tid = threadIdx.x;
    int r_ = tid >> 2, q_ = tid & 3;
    int kh = tid >> 5, c2 = (tid & 31) * 2;
    int lane = tid & 31, g = lane >> 2, q = lane & 3;
    int warp = tid >> 5, mw = (warp & 3) * 16, nw = (warp >> 2) * 32;
    float4 ar = *(const float4*)&Az[(long)r_ * ldA + q_ * 4];
    float2 be = *(const float2*)&Bz[(long)(2 * kh) * ldB + c2];
    float2 bo = *(const float2*)&Bz[(long)(2 * kh + 1) * ldB + c2];
    for (int k0 = 0; k0 < K; k0 += 16) {
        uint2 h, l;
        bsplit4(ar, h, l);
        *(uint2*)&Ah[r_ * SKH + q_ * 2] = h;
        *(uint2*)&Al[r_ * SKH + q_ * 2] = l;
        unsigned h0, l0, h1, l1;
        bsplit2(be.x, bo.x, h0, l0);
        bsplit2(be.y, bo.y, h1, l1);
        *(uint2*)&Bh[kh * SBN + c2] = make_uint2(h0, h1);
        *(uint2*)&Bl[kh * SBN + c2] = make_uint2(l0, l1);
        __syncthreads();
        int kn = k0 + 16;
        if (kn < K) {
            ar = *(const float4*)&Az[(long)r_ * ldA + kn + q_ * 4];
            be = *(const float2*)&Bz[(long)(kn + 2 * kh) * ldB + c2];
            bo = *(const float2*)&Bz[(long)(kn + 2 * kh + 1) * ldB + c2];
        }
        warp_bmma<true>(Ah, Al, Bh, Bl, mw, nw, g, q, acc);
        __syncthreads();
    }
}

// NT BM=128, A fp32 inline-split, B pre-split (scalar loads).
__device__ __forceinline__ void loop128_nt_pb(const float* __restrict__ Az, int ldA,
                                              const unsigned* __restrict__ Bhg,
                                              const unsigned* __restrict__ Blg, int ldBp,
                                              int K, unsigned* Ah, unsigned* Al,
                                              unsigned* Bh, unsigned* Bl, float acc[2][4][4]) {
    int tid = threadIdx.x;
    int r_ = tid >> 2, q_ = tid & 3;
    int lane = tid & 31, g = lane >> 2, q = lane & 3;
    int warp = tid >> 5, mw = (warp & 3) * 16, nw = (warp >> 2) * 32;
    int aoff = r_ * SKH + q_ * 2;
    int aoff2 = (r_ + 64) * SKH + q_ * 2;
    long bbase = (long)r_ * ldBp + q_ * 2;
    float4 a0 = *(const float4*)&Az[(long)r_ * ldA + q_ * 4];
    float4 a1 = *(const float4*)&Az[(long)(r_ + 64) * ldA + q_ * 4];
    unsigned bh0 = Bhg[bbase], bh1 = Bhg[bbase + 1];
    unsigned bl0 = Blg[bbase], bl1 = Blg[bbase + 1];
    for (int k0 = 0; k0 < K; k0 += 16) {
        uint2 h, l;
        bsplit4(a0, h, l);
        *(uint2*)&Ah[aoff] = h; *(uint2*)&Al[aoff] = l;
        bsplit4(a1, h, l);
        *(uint2*)&Ah[aoff2] = h; *(uint2*)&Al[aoff2] = l;
        *(uint2*)&Bh[aoff] = make_uint2(bh0, bh1);
        *(uint2*)&Bl[aoff] = make_uint2(bl0, bl1);
        __syncthreads();
        int kn = k0 + 16;
        if (kn < K) {
            a0 = *(const float4*)&Az[(long)r_ * ldA + kn + q_ * 4];
            a1 = *(const float4*)&Az[(long)(r_ + 64) * ldA + kn + q_ * 4];
            long bo = bbase + kn / 2;
            bh0 = Bhg[bo]; bh1 = Bhg[bo + 1];
            bl0 = Blg[bo]; bl1 = Blg[bo + 1];
        }
        warp_bmma128(Ah, Al, Bh, Bl, mw, nw, g, q, acc);
        __syncthreads();
    }
}

// NT BM=128, BOTH operands pre-split (scores), all scalar global loads.
__device__ __forceinline__ void loop128_pp(const unsigned* __restrict__ Ahg,
                                           const unsigned* __restrict__ Alg, int ldAp,
                                           const unsigned* __restrict__ Bhg,
                                           const unsigned* __restrict__ Blg, int ldBp,
                                           int K, unsigned* Ah, unsigned* Al,
                                           unsigned* Bh, unsigned* Bl, float acc[2][4][4]) {
    int tid = threadIdx.x;
    int r_ = tid >> 2, q_ = tid & 3;
    int lane = tid & 31, g = lane >> 2, q = lane & 3;
    int warp = tid >> 5, mw = (warp & 3) * 16, nw = (warp >> 2) * 32;
    int aoff = r_ * SKH + q_ * 2;
    int aoff2 = (r_ + 64) * SKH + q_ * 2;
    long abase0 = (long)r_ * ldAp + q_ * 2;
    long abase1 = (long)(r_ + 64) * ldAp + q_ * 2;
    long bbase = (long)r_ * ldBp + q_ * 2;
    unsigned a0h0 = Ahg[abase0], a0h1 = Ahg[abase0 + 1];
    unsigned a0l0 = Alg[abase0], a0l1 = Alg[abase0 + 1];
    unsigned a1h0 = Ahg[abase1], a1h1 = Ahg[abase1 + 1];
    unsigned a1l0 = Alg[abase1], a1l1 = Alg[abase1 + 1];
    unsigned bh0 = Bhg[bbase], bh1 = Bhg[bbase + 1];
    unsigned bl0 = Blg[bbase], bl1 = Blg[bbase + 1];
    for (int k0 = 0; k0 < K; k0 += 16) {
        *(uint2*)&Ah[aoff]  = make_uint2(a0h0, a0h1);
        *(uint2*)&Al[aoff]  = make_uint2(a0l0, a0l1);
        *(uint2*)&Ah[aoff2] = make_uint2(a1h0, a1h1);
        *(uint2*)&Al[aoff2] = make_uint2(a1l0, a1l1);
        *(uint2*)&Bh[aoff]  = make_uint2(bh0, bh1);
        *(uint2*)&Bl[aoff]  = make_uint2(bl0, bl1);
        __syncthreads();
        int kn = k0 + 16;
        if (kn < K) {
            int d = kn / 2;
            a0h0 = Ahg[abase0 + d]; a0h1 = Ahg[abase0 + d + 1];
            a0l0 = Alg[abase0 + d]; a0l1 = Alg[abase0 + d + 1];
            a1h0 = Ahg[abase1 + d]; a1h1 = Ahg[abase1 + d + 1];
            a1l0 = Alg[abase1 + d]; a1l1 = Alg[abase1 + d + 1];
            bh0 = Bhg[bbase + d]; bh1 = Bhg[bbase + d + 1];
            bl0 = Blg[bbase + d]; bl1 = Blg[bbase + d + 1];
        }
        warp_bmma128(Ah, Al, Bh, Bl, mw, nw, g, q, acc);
        __syncthreads();
    }
}

// ---------------- epilogues ----------------
__device__ __forceinline__ void epi_tile(float* C, int ldC, int row, int col,
                                         const float v[4], const float* bias,
                                         float alpha, bool prelu) {
    float b0 = 0.f, b1 = 0.f;
    if (bias) { b0 = bias[col]; b1 = bias[col + 1]; }
    float v00 = v[0] + b0, v01 = v[1] + b1, v10 = v[2] + b0, v11 = v[3] + b1;
    if (prelu) {
        v00 = (v00 >= 0.f) ? v00 : alpha * v00;
        v01 = (v01 >= 0.f) ? v01 : alpha * v01;
        v10 = (v10 >= 0.f) ? v10 : alpha * v10;
        v11 = (v11 >= 0.f) ? v11 : alpha * v11;
    }
    *(float2*)&C[(long)row * ldC + col]       = make_float2(v00, v01);
    *(float2*)&C[(long)(row + 8) * ldC + col] = make_float2(v10, v11);
}

__device__ __forceinline__ void epi64(float* C, int ldC, int m0, int n0,
                                      float acc[4][4], const float* bias,
                                      float alpha, bool prelu) {
    int tid = threadIdx.x, lane = tid & 31, g = lane >> 2, q = lane & 3;
    int warp = tid >> 5, mw = (warp & 3) * 16, nw = (warp >> 2) * 32;
    int row = m0 + mw + g;
#pragma unroll
    for (int j = 0; j < 4; j++)
        epi_tile(C, ldC, row, n0 + nw + 8 * j + 2 * q, acc[j], bias, alpha, prelu);
}

__device__ __forceinline__ void epi128(float* C, int ldC, int m0, int n0,
                                       float acc[2][4][4], const float* bias,
                                       float alpha, bool prelu) {
    int tid = threadIdx.x, lane = tid & 31, g = lane >> 2, q = lane & 3;
    int warp = tid >> 5, mw = (warp & 3) * 16, nw = (warp >> 2) * 32;
#pragma unroll
    for (int i = 0; i < 2; i++) {
        int row = m0 + mw + i * 64 + g;
#pragma unroll
        for (int j = 0; j < 4; j++)
            epi_tile(C, ldC, row, n0 + nw + 8 * j + 2 * q, acc[i][j], bias, alpha, prelu);
    }
}

__device__ __forceinline__ void epi128_pack(unsigned* Ch, unsigned* Cl, int ldp,
                                            int m0, int n0, float acc[2][4][4],
                                            const float* bias) {
    int tid = threadIdx.x, lane = tid & 31, g = lane >> 2, q = lane & 3;
    int warp = tid >> 5, mw = (warp & 3) * 16, nw = (warp >> 2) * 32;
#pragma unroll
    for (int i = 0; i < 2; i++) {
        int row = m0 + mw + i * 64 + g;
#pragma unroll
        for (int j = 0; j < 4; j++) {
            int col = n0 + nw + 8 * j + 2 * q;
            float b0 = bias[col], b1 = bias[col + 1];
            unsigned h, l;
            bsplit2(acc[i][j][0] + b0, acc[i][j][1] + b1, h, l);
            Ch[(long)row * ldp + col / 2] = h;
            Cl[(long)row * ldp + col / 2] = l;
            bsplit2(acc[i][j][2] + b0, acc[i][j][3] + b1, h, l);
            Ch[(long)(row + 8) * ldp + col / 2] = h;
            Cl[(long)(row + 8) * ldp + col / 2] = l;
        }
    }
}

// =============== weight pre-split ===============
__global__ void k_wsplit(const float* __restrict__ fc_w, const float* __restrict__ qw,
                         const float* __restrict__ kw, const float* __restrict__ vw,
                         const float* __restrict__ rw, const float* __restrict__ l1w,
                         const float* __restrict__ l2w, const float* __restrict__ m1w,
                         unsigned* __restrict__ Wh, unsigned* __restrict__ Wl) {
    int i = blockIdx.x * 256 + threadIdx.x;
    if (i >= WTOT) return;
    const float* src; int rel;
    if (i < OFF_Q)       { src = fc_w; rel = i - OFF_FC; }
    else if (i < OFF_K)  { src = qw;   rel = i - OFF_Q; }
    else if (i < OFF_V)  { src = kw;   rel = i - OFF_K; }
    else if (i < OFF_R)  { src = vw;   rel = i - OFF_V; }
    else if (i < OFF_L1) { src = rw;   rel = i - OFF_R; }
    else if (i < OFF_L2) { src = l1w;  rel = i - OFF_L1; }
    else if (i < OFF_M1) { src = l2w;  rel = i - OFF_L2; }
    else                 { src = m1w;  rel = i - OFF_M1; }
    float a = src[2 * rel], b = src[2 * rel + 1];
    unsigned h, l;
    bsplit2(a, b, h, l);
    Wh[i] = h; Wl[i] = l;
}

// =============== generic NT 64x64 GEMM, pre-split B ===============
template<bool ADD2>
__global__ void __launch_bounds__(256, 3) k_gemm64(
    const float* __restrict__ A, const float* __restrict__ A2,
    const unsigned* __restrict__ BhG, const unsigned* __restrict__ BlG,
    const float* __restrict__ bias, float* __restrict__ C, int Nc, int K,
    long sAz, int ldA, long sBzp, int ldBp, int bMod, long sCz, int ldC,
    const float* __restrict__ alpha_ptr)
{
    __shared__ __align__(16) unsigned Ah[AS64], Al[AS64];
    __shared__ __align__(16) unsigned Bh[AS64], Bl[AS64];
    int z = blockIdx.z;
    int m0 = blockIdx.y * 64, n0 = blockIdx.x * 64;
    int wz = z % bMod;
    const float* Az = A + (long)z * sAz + (long)m0 * ldA;
    const unsigned* Bhz = BhG + (long)wz * sBzp + (long)n0 * ldBp;
    const unsigned* Blz = BlG + (long)wz * sBzp + (long)n0 * ldBp;
    float* Cz = C + (long)z * sCz;

    float acc[4][4] = {};
    loop64_nt_pb<ADD2>(Az, ADD2 ? (A2 + (long)z * sAz + (long)m0 * ldA) : nullptr, ldA,
                       Bhz, Blz, ldBp, K, Ah, Al, Bh, Bl, acc);
    float alpha = alpha_ptr ? *alpha_ptr : 0.f;
    epi64(Cz, ldC, m0, n0, acc, bias ? (bias + wz * Nc) : nullptr,
          alpha, alpha_ptr != nullptr);
}

// =============== feats (R9 exact) ===============
__global__ void __launch_bounds__(256, 3) k_feats(
    const float* __restrict__ Tm, const float* __restrict__ theta,
    const float* __restrict__ Ab, const float* __restrict__ H,
    float* __restrict__ P, int l)
{
    __shared__ __align__(16) unsigned A0h[AS64], A0l[AS64];
    __shared__ __align__(16) unsigned A1h[AS64], A1l[AS64];
    __shared__ __align__(16) unsigned B0h[BSNN], B0l[BSNN];
    __shared__ __align__(16) unsigned B1h[BSNN], B1l[BSNN];
    int z = blockIdx.z;
    int r = z % K_R, chunk = z / K_R;
    const float* T0 = Tm + (long)((l * K_R + r) * K_E) * NN1;
    const float* T1 = T0 + NN1;
    const float* T2 = T1 + NN1;
    const float* A0 = Ab + (long)r * NN1;
    const float* A1 = Ab + (long)(K_R + r) * NN1;
    const float* H0 = H + (long)r * NF1;
    const float* H1 = H + (long)(K_R + r) * NF1;
    float* C0 = P + (long)(chunk * (K_B * K_R) + r) * NF1;
    float* C1 = P + (long)(chunk * (K_B * K_R) + K_R + r) * NF1;
    float t0 = theta[(l * K_R + r) * K_E + 0];
    float t1 = theta[(l * K_R + r) * K_E + 1];
    float t2 = theta[(l * K_R + r) * K_E + 2];
    int m0 = blockIdx.y * 64;
    int Ks = chunk * (K_N / 2), Ke = Ks + K_N / 2;

    int tid = threadIdx.x;
    int r_ = tid >> 2, q_ = tid & 3;
    int kh = tid >> 5, c2 = (tid & 31) * 2;
    int lane = tid & 31, g = lane >> 2, q = lane & 3;
    int warp = tid >> 5, mw = (warp & 3) * 16, nw = (warp >> 2) * 32;

    float acc0[4][4] = {}, acc1[4][4] = {};

    float4 tv0, tv1, tv2, av0, av1;
    float2 h0e, h0o, h1e, h1o;
    {
        long off = (long)(m0 + r_) * K_N + Ks + q_ * 4;
        tv0 = *(const float4*)(T0 + off); tv1 = *(const float4*)(T1 + off);
        tv2 = *(const float4*)(T2 + off);
        av0 = *(const float4*)(A0 + off); av1 = *(const float4*)(A1 + off);
        h0e = *(const float2*)&H0[(long)(Ks + 2 * kh) * K_F + c2];
        h0o = *(const float2*)&H0[(long)(Ks + 2 * kh + 1) * K_F + c2];
        h1e = *(const float2*)&H1[(long)(Ks + 2 * kh) * K_F + c2];
        h1o = *(const float2*)&H1[(long)(Ks + 2 * kh + 1) * K_F + c2];
    }
    for (int k0 = Ks; k0 < Ke; k0 += 16) {
        float4 sv;
        sv.x = t0 * tv0.x + t1 * tv1.x + t2 * tv2.x;
        sv.y = t0 * tv0.y + t1 * tv1.y + t2 * tv2.y;
        sv.z = t0 * tv0.z + t1 * tv1.z + t2 * tv2.z;
        sv.w = t0 * tv0.w + t1 * tv1.w + t2 * tv2.w;
        float4 sa0 = make_float4(sv.x * av0.x, sv.y * av0.y, sv.z * av0.z, sv.w * av0.w);
        float4 sa1 = make_float4(sv.x * av1.x, sv.y * av1.y, sv.z * av1.z, sv.w * av1.w);
        uint2 h, l;
        bsplit4(sa0, h, l);
        *(uint2*)&A0h[r_ * SKH + q_ * 2] = h;
        *(uint2*)&A0l[r_ * SKH + q_ * 2] = l;
        bsplit4(sa1, h, l);
        *(uint2*)&A1h[r_ * SKH + q_ * 2] = h;
        *(uint2*)&A1l[r_ * SKH + q_ * 2] = l;
        unsigned hh0, ll0, hh1, ll1;
        bsplit2(h0e.x, h0o.x, hh0, ll0);
        bsplit2(h0e.y, h0o.y, hh1, ll1);
        *(uint2*)&B0h[kh * SBN + c2] = make_uint2(hh0, hh1);
        *(uint2*)&B0l[kh * SBN + c2] = make_uint2(ll0, ll1);
        bsplit2(h1e.x, h1o.x, hh0, ll0);
        bsplit2(h1e.y, h1o.y, hh1, ll1);
        *(uint2*)&B1h[kh * SBN + c2] = make_uint2(hh0, hh1);
        *(uint2*)&B1l[kh * SBN + c2] = make_uint2(ll0, ll1);
        __syncthreads();
        int kn = k0 + 16;
        if (kn < Ke) {
            long off = (long)(m0 + r_) * K_N + kn + q_ * 4;
            tv0 = *(const float4*)(T0 + off); tv1 = *(const float4*)(T1 + off);
            tv2 = *(const float4*)(T2 + off);
            av0 = *(const float4*)(A0 + off); av1 = *(const float4*)(A1 + off);
            h0e = *(const float2*)&H0[(long)(kn + 2 * kh) * K_F + c2];
            h0o = *(const float2*)&H0[(long)(kn + 2 * kh + 1) * K_F + c2];
            h1e = *(const float2*)&H1[(long)(kn + 2 * kh) * K_F + c2];
            h1o = *(const float2*)&H1[(long)(kn + 2 * kh + 1) * K_F + c2];
        }
        warp_bmma<true>(A0h, A0l, B0h, B0l, mw, nw, g, q, acc0);
        warp_bmma<true>(A1h, A1l, B1h, B1l, mw, nw, g, q, acc1);
        __syncthreads();
    }
    epi64(C0, K_F, m0, 0, acc0, nullptr, 0.f, false);
    epi64(C1, K_F, m0, 0, acc1, nullptr, 0.f, false);
}

// =============== fused q,k,v + ts projections, BM=128, pre-split weights ===============
__global__ void __launch_bounds__(256, 2) k_qkv_ts(
    const float* __restrict__ h, const float* __restrict__ skip,
    const unsigned* __restrict__ Wh, const unsigned* __restrict__ Wl,
    const float* __restrict__ qb, const float* __restrict__ kb, const float* __restrict__ vb,
    const float* __restrict__ l1b, int l,
    unsigned* __restrict__ qh, unsigned* __restrict__ ql,
    unsigned* __restrict__ kh, unsigned* __restrict__ kl,
    float* __restrict__ v, float* __restrict__ cat)
{
    __shared__ __align__(16) unsigned Ahs[AS128], Als[AS128];
    __shared__ __align__(16) unsigned Bhs[AS64], Bls[AS64];
    int x = blockIdx.x;
    int m0 = blockIdx.y * 128;
    const float *A, *bb;
    const unsigned *Bhg, *Blg;
    int n0, ldBp, K;
    if (x < 12) {
        int which = x >> 2; n0 = (x & 3) * 64;
        A = h;
        long base = (which == 0 ? OFF_Q : which == 1 ? OFF_K : OFF_V)
                  + (long)l * 256 * 160 + (long)n0 * 160;
        Bhg = Wh + base; Blg = Wl + base;
        bb = (which == 0) ? qb : (which == 1) ? kb : vb;
        ldBp = 160; K = K_INRET;
    } else {
        n0 = (x - 12) * 64;
        A = skip;
        long base = OFF_L1 + (long)l * 128 * 160 + (long)n0 * 160;
        Bhg = Wh + base; Blg = Wl + base;
        bb = l1b;
        ldBp = 160; K = K_HRET;
    }
    float acc[2][4][4] = {};
    loop128_nt_pb(A + (long)m0 * K_INRET, K_INRET, Bhg, Blg, ldBp, K,
                  Ahs, Als, Bhs, Bls, acc);
    if (x < 12) {
        int which = x >> 2;
        if (which == 0)      epi128_pack(qh, ql, 128, m0, n0, acc, bb);
        else if (which == 1) epi128_pack(kh, kl, 128, m0, n0, acc, bb);
        else                 epi128(v, K_INTER, m0, n0, acc, bb, 0.f, false);
    } else {
        epi128(cat + K_OUTRET, K_CAT, m0, n0, acc, bb, 0.f, false);
    }
}

// =============== triangular masked scores, BM=128, both operands pre-split ===============
__global__ void __launch_bounds__(256, 2) k_scores(
    const unsigned* __restrict__ qh, const unsigned* __restrict__ ql,
    const unsigned* __restrict__ kh, const unsigned* __restrict__ kl,
    float* __restrict__ ms)
{
    __shared__ __align__(16) unsigned Ahs[AS128], Als[AS128];
    __shared__ __align__(16) unsigned Bhs[AS64], Bls[AS64];
    int i = blockIdx.x;
    int mt = (int)((sqrtf(4.f * i + 1.f) - 1.f) * 0.5f);
    while (mt * mt + mt > i) mt--;
    while ((mt + 1) * (mt + 1) + (mt + 1) <= i) mt++;
    int nt = i - mt * mt - mt;
    int m0 = mt * 128, n0 = nt * 64;
    int z = blockIdx.y;
    const unsigned* Ahg = qh + (long)z * K_N * 128 + (long)m0 * 128;
    const unsigned* Alg = ql + (long)z * K_N * 128 + (long)m0 * 128;
    const unsigned* Bhg = kh + (long)z * K_N * 128 + (long)n0 * 128;
    const unsigned* Blg = kl + (long)z * K_N * 128 + (long)n0 * 128;
    float* Cz = ms + (long)z * NN1;

    float acc[2][4][4] = {};
    loop128_pp(Ahg, Alg, 128, Bhg, Blg, 128, K_INTER, Ahs, Als, Bhs, Bls, acc);

    int tid = threadIdx.x, lane = tid & 31, g = lane >> 2, qq = lane & 3;
    int warp = tid >> 5, mw = (warp & 3) * 16, nw = (warp >> 2) * 32;
#pragma unroll
    for (int i2 = 0; i2 < 2; i2++) {
        int row = m0 + mw + i2 * 64 + g;
#pragma unroll
        for (int j = 0; j < 4; j++) {
            int col = n0 + nw + 8 * j + 2 * qq;
            float v00 = (row > col)         ? INV_GAMMA * acc[i2][j][0] : 0.f;
            float v01 = (row > col + 1)     ? INV_GAMMA * acc[i2][j][1] : 0.f;
            float v10 = (row + 8 > col)     ? INV_GAMMA * acc[i2][j][2] : 0.f;
            float v11 = (row + 8 > col + 1) ? INV_GAMMA * acc[i2][j][3] : 0.f;
            *(float2*)&Cz[(long)row * K_N + col]       = make_float2(v00, v01);
            *(float2*)&Cz[(long)(row + 8) * K_N + col] = make_float2(v10, v11);
        }
    }
}

// =============== ret = ms @ v (R9 exact) ===============
__global__ void __launch_bounds__(256, 3) k_ret(
    const float* __restrict__ ms, const float* __restrict__ v, float* __restrict__ P)
{
    __shared__ __align__(16) unsigned Ah[AS64], Al[AS64];
    __shared__ __align__(16) unsigned Bh[BSNN], Bl[BSNN];
    int z = blockIdx.z;
    int b = z & 1, chunk = z >> 1;
    int m0 = blockIdx.y * 64, n0 = blockIdx.x * 64;
    int Keff = m0 + 64;
    int half = Keff >> 1;
    int Ks = chunk ? half : 0;
    int Ke = chunk ? Keff : half;
    const float* Az = ms + (long)b * NN1 + (long)m0 * K_N + Ks;
    const float* Bz = v + (long)b * K_N * K_INTER + (long)Ks * K_INTER + n0;
    float* Cz = P + (long)chunk * PHALF + (long)b * K_N * K_OUTRET;

    float acc[4][4] = {};
    loop64_nn(Az, K_N, Bz, K_INTER, Ke - Ks, Ah, Al, Bh, Bl, acc);
    epi64(Cz, K_OUTRET, m0, n0, acc, nullptr, 0.f, false);
}

// =============== eta (pre-split rw) ===============
__global__ void __launch_bounds__(256, 3) k_eta(
    const float* __restrict__ P, const unsigned* __restrict__ Wh,
    const unsigned* __restrict__ Wl, const float* __restrict__ rb,
    const float* __restrict__ a_ret, int l, float* __restrict__ cat)
{
    __shared__ __align__(16) unsigned Ah[AS64], Al[AS64];
    __shared__ __align__(16) unsigned Bh[AS64], Bl[AS64];
    int n0 = blockIdx.x * 64, m0 = blockIdx.y * 64;
    long base = OFF_R + (long)l * 256 * 128 + (long)n0 * 128;
    float acc[4][4] = {};
    loop64_nt_pb<true>(P + (long)m0 * K_OUTRET, P + PHALF + (long)m0 * K_OUTRET,
                       K_OUTRET, Wh + base, Wl + base, 128, K_INTER,
                       Ah, Al, Bh, Bl, acc);
    epi64(cat, K_CAT, m0, n0, acc, rb, *a_ret, true);
}

// ---------------- conv over relations + PReLU ----------------
__global__ void k_conv(const float* __restrict__ diff, const float* __restrict__ cw,
                       const float* __restrict__ cb, const float* __restrict__ a1,
                       int l, float* __restrict__ u) {
    const int PQ = K_N * K_F / 4;
    int i = blockIdx.x * 256 + threadIdx.x;
    if (i >= K_B * K_R * PQ) return;
    int pq = i % PQ; int s = (i / PQ) % K_R; int b = i / (PQ * K_R);
    float bb = cb[l * K_R + s];
    float4 acc = make_float4(bb, bb, bb, bb);
    const float4* d4 = (const float4*)diff;
#pragma unroll
    for (int r2 = 0; r2 < K_R; r2++) {
        float w = cw[(l * K_R + s) * K_R + r2];
        float4 v = d4[(long)(b * K_R + r2) * PQ + pq];
        acc.x += w * v.x; acc.y += w * v.y; acc.z += w * v.z; acc.w += w * v.w;
    }
    float al = a1[l];
    acc.x = (acc.x >= 0.f) ? acc.x : al * acc.x;
    acc.y = (acc.y >= 0.f) ? acc.y : al * acc.y;
    acc.z = (acc.z >= 0.f) ? acc.z : al * acc.z;
    acc.w = (acc.w >= 0.f) ? acc.w : al * acc.w;
    ((float4*)u)[i] = acc;
}

// ---------------- initial skip transpose ----------------
__global__ void k_skip0(const float* __restrict__ x, float* __restrict__ sk) {
    int i = blockIdx.x * 256 + threadIdx.x;
    if (i >= K_B * K_N * K_R * K_F) return;
    int d = i % K_F;
    int r = (i / K_F) % K_R;
    int n = (i / (K_F * K_R)) % K_N;
    int b = i / (K_F * K_R * K_N);
    sk[i] = x[(((long)b * K_R + r) * K_N + n) * K_F + d];
}

// ---------------- final tiny GEMM: out[2048,2] ----------------
__global__ void k_mlp2(const float* __restrict__ m1, const float* __restrict__ w,
                       const float* __restrict__ b, float* __restrict__ out) {
    __shared__ float ws[2 * K_H1];
    int tid = threadIdx.x;
    if (tid < 2 * K_H1) ws[tid] = w[tid];
    __syncthreads();
    int row = blockIdx.x * 256 + tid;
    const float4* mr = (const float4*)(m1 + (long)row * K_H1);
    float s0 = 0.f, s1 = 0.f;
#pragma unroll
    for (int i = 0; i < K_H1 / 4; i++) {
        float4 v = mr[i];
        s0 += v.x * ws[i * 4] + v.y * ws[i * 4 + 1] + v.z * ws[i * 4 + 2] + v.w * ws[i * 4 + 3];
        s1 += v.x * ws[K_H1 + i * 4] + v.y * ws[K_H1 + i * 4 + 1]
            + v.z * ws[K_H1 + i * 4 + 2] + v.w * ws[K_H1 + i * 4 + 3];
    }
    out[(long)row * 2]     = s0 + b[0];
    out[(long)row * 2 + 1] = s1 + b[1];
}

// ---------------- host launcher ----------------
extern "C" void kernel_launch(void* const* d_in, const int* in_sizes, int n_in,
                              void* d_out, int out_size) {
    const float* x      = (const float*)d_in[0];
    const float* a      = (const float*)d_in[1];
    const float* T      = (const float*)d_in[2];
    const float* theta  = (const float*)d_in[3];
    const float* fc_w   = (const float*)d_in[4];
    const float* fc_b   = (const float*)d_in[5];
    const float* conv_w = (const float*)d_in[6];
    const float* conv_b = (const float*)d_in[7];
    const float* a0     = (const float*)d_in[8];
    const float* a1     = (const float*)d_in[9];
    const float* qw = (const float*)d_in[10]; const float* qb = (const float*)d_in[11];
    const float* kw = (const float*)d_in[12]; const float* kb = (const float*)d_in[13];
    const float* vw = (const float*)d_in[14]; const float* vb = (const float*)d_in[15];
    const float* rw = (const float*)d_in[16]; const float* rb = (const float*)d_in[17];
    const float* a_ret = (const float*)d_in[18];
    const float* l1w = (const float*)d_in[19]; const float* l1b = (const float*)d_in[20];
    const float* l2w = (const float*)d_in[21]; const float* l2b = (const float*)d_in[22];
    const float* m1w = (const float*)d_in[23]; const float* m1b = (const float*)d_in[24];
    const float* m2w = (const float*)d_in[25]; const float* m2b = (const float*)d_in[26];
    const float* a_mlp = (const float*)d_in[27];
    float* out = (float*)d_out;

    float *P, *diff, *h, *v, *ms, *cat, *skA, *skB, *m1;
    unsigned *Wh, *Wl, *qh, *ql, *kh, *kl;
    cudaGetSymbolAddress((void**)&P, g_P);
    cudaGetSymbolAddress((void**)&diff, g_diff);
    cudaGetSymbolAddress((void**)&h, g_h);
    cudaGetSymbolAddress((void**)&v, g_v);
    cudaGetSymbolAddress((void**)&ms, g_ms);
    cudaGetSymbolAddress((void**)&cat, g_cat);
    cudaGetSymbolAddress((void**)&skA, g_skipA);
    cudaGetSymbolAddress((void**)&skB, g_skipB);
    cudaGetSymbolAddress((void**)&m1, g_m1);
    cudaGetSymbolAddress((void**)&Wh, g_Wh);
    cudaGetSymbolAddress((void**)&Wl, g_Wl);
    cudaGetSymbolAddress((void**)&qh, g_qh);
    cudaGetSymbolAddress((void**)&ql, g_ql);
    cudaGetSymbolAddress((void**)&kh, g_kh);
    cudaGetSymbolAddress((void**)&kl, g_kl);

    const int M2 = K_B * K_N;  // 2048

    k_wsplit<<<(WTOT + 255) / 256, 256>>>(fc_w, qw, kw, vw, rw, l1w, l2w, m1w, Wh, Wl);

    { int tot = K_B * K_N * K_R * K_F;
      k_skip0<<<(tot + 255) / 256, 256>>>(x, skA); }

    const float* hc = x;
    float* sin_ = skA;
    float* sout = skB;

    for (int l = 0; l < 2; l++) {
        k_feats<<<dim3(1, K_N / 64, K_B * K_R), 256>>>(T, theta, a, hc, P, l);

        k_gemm64<true><<<dim3(1, K_N / 64, K_B * K_R), 256>>>(
            P, P + (long)K_B * K_R * NF1,
            Wh + OFF_FC + (long)l * K_R * 2048, Wl + OFF_FC + (long)l * K_R * 2048,
            fc_b + (long)l * K_R * K_F, diff,
            K_F, K_F, NF1, K_F, 2048, 32, K_R, NF1, K_F, a0 + l);

        { int tot = K_B * K_R * K_N * K_F / 4;
          k_conv<<<(tot + 255) / 256, 256>>>(diff, conv_w, conv_b, a1, l, h); }
        hc = h;

        k_qkv_ts<<<dim3(14, K_N * K_B / 128), 256>>>(
            h, sin_, Wh, Wl,
            qb + (long)l * K_INTER, kb + (long)l * K_INTER, vb + (long)l * K_INTER,
            l1b + (long)l * K_H1, l,
            qh, ql, kh, kl, v, cat);

        k_scores<<<dim3(72, 2), 256>>>(qh, ql, kh, kl, ms);

        k_ret<<<dim3(K_OUTRET / 64, K_N / 64, 4), 256>>>(ms, v, P);

        k_eta<<<dim3(K_OUTRET / 64, M2 / 64), 256>>>(
            P, Wh, Wl, rb + (long)l * K_OUTRET, a_ret + l, l, cat);

        k_gemm64<false><<<dim3(K_HRET / 64, M2 / 64, 1), 256>>>(
            cat, nullptr,
            Wh + OFF_L2 + (long)l * 320 * 192, Wl + OFF_L2 + (long)l * 320 * 192,
            l2b + (long)l * K_HRET, sout,
            K_HRET, K_CAT, 0, K_CAT, 0, 192, 1, 0, K_HRET, nullptr);

        float* t0 = sin_; sin_ = sout; sout = t0;
    }

    k_gemm64<false><<<dim3(K_H1 / 64, M2 / 64, 1), 256>>>(
        sin_, nullptr, Wh + OFF_M1, Wl + OFF_M1, m1b, m1,
        K_H1, K_HRET, 0, K_HRET, 0, 160, 1, 0, K_H1, a_mlp);
    k_mlp2<<<M2 / 256, 256>>>(m1, m2w, m2b, out);
}

// round 16
// speedup vs baseline: 1.0378x; 1.0378x over previous
#include <cuda_runtime.h>
#include <cuda_bf16.h>

#define K_B 2
#define K_R 5
#define K_N 1024
#define K_E 3
#define K_F 64
#define K_INRET 320
#define K_INTER 256
#define K_OUTRET 256
#define K_H1 128
#define K_HRET 320
#define K_CAT 384
#define INV_GAMMA 0.4f
#define SKH 12    // row-major bf16x2 tile stride (8 k-pairs + 4 pad)
#define SBN 72    // k-pair-major NN B tile stride
#define NN1 (K_N * K_N)
#define NF1 (K_N * K_F)
#define AS64 (64 * SKH)
#define AS128 (128 * SKH)
#define BSNN (8 * SBN)

// ---------------- device scratch ----------------
__device__ __align__(16) float g_P[2 * K_B * K_R * K_N * K_F];  // feats partials / ret
__device__ __align__(16) float g_diff [K_B * K_R * K_N * K_F];
__device__ __align__(16) float g_h    [K_B * K_R * K_N * K_F];
__device__ __align__(16) float g_q [K_B * K_N * K_INTER];
__device__ __align__(16) float g_k [K_B * K_N * K_INTER];
__device__ __align__(16) float g_v [K_B * K_N * K_INTER];
__device__ __align__(16) float g_ms[K_B * K_N * K_N];
__device__ __align__(16) float g_cat[K_B * K_N * K_CAT];
__device__ __align__(16) float g_skipA[K_B * K_N * K_HRET];
__device__ __align__(16) float g_skipB[K_B * K_N * K_HRET];
__device__ __align__(16) float g_m1[K_B * K_N * K_H1];

// ---------------- bf16 split helpers ----------------
__device__ __forceinline__ unsigned as_u(__nv_bfloat162 v) {
    return reinterpret_cast<unsigned&>(v);
}
__device__ __forceinline__ void bsplit4(float4 v, uint2& hi, uint2& lo) {
    __nv_bfloat162 h01 = __floats2bfloat162_rn(v.x, v.y);
    __nv_bfloat162 h23 = __floats2bfloat162_rn(v.z, v.w);
    float r0 = v.x - __bfloat162float(h01.x);
    float r1 = v.y - __bfloat162float(h01.y);
    float r2 = v.z - __bfloat162float(h23.x);
    float r3 = v.w - __bfloat162float(h23.y);
    __nv_bfloat162 l01 = __floats2bfloat162_rn(r0, r1);
    __nv_bfloat162 l23 = __floats2bfloat162_rn(r2, r3);
    hi = make_uint2(as_u(h01), as_u(h23));
    lo = make_uint2(as_u(l01), as_u(l23));
}
__device__ __forceinline__ void bsplit2(float a, float b, unsigned& hi, unsigned& lo) {
    __nv_bfloat162 h = __floats2bfloat162_rn(a, b);
    float ra = a - __bfloat162float(h.x);
    float rb = b - __bfloat162float(h.y);
    __nv_bfloat162 l = __floats2bfloat162_rn(ra, rb);
    hi = as_u(h); lo = as_u(l);
}

__device__ __forceinline__ void mmabf(float acc[4], const unsigned a[4], const unsigned b[2]) {
    asm volatile(
        "mma.sync.aligned.m16n8k16.row.col.f32.bf16.bf16.f32 "
        "{%0,%1,%2,%3}, {%4,%5,%6,%7}, {%8,%9}, {%0,%1,%2,%3};"
        : "+f"(acc[0]), "+f"(acc[1]), "+f"(acc[2]), "+f"(acc[3])
        : "r"(a[0]), "r"(a[1]), "r"(a[2]), "r"(a[3]), "r"(b[0]), "r"(b[1]));
}

__device__ __forceinline__ void lda_bf(const unsigned* A, int mrow, int g, int q,
                                       unsigned a[4]) {
    const unsigned* p = &A[(mrow + g) * SKH + q];
    a[0] = p[0];
    a[1] = p[8 * SKH];
    a[2] = p[4];
    a[3] = p[8 * SKH + 4];
}
__device__ __forceinline__ void ldb_nt(const unsigned* B, int nrow, int g, int q,
                                       unsigned b[2]) {
    const unsigned* p = &B[(nrow + g) * SKH + q];
    b[0] = p[0]; b[1] = p[4];
}
__device__ __forceinline__ void ldb_nn(const unsigned* B, int ncol, int g, int q,
                                       unsigned b[2]) {
    b[0] = B[q * SBN + ncol + g];
    b[1] = B[(q + 4) * SBN + ncol + g];
}

template<bool BNN>
__device__ __forceinline__ void warp_bmma(const unsigned* Ah, const unsigned* Al,
                                          const unsigned* Bh, const unsigned* Bl,
                                          int mw, int nw, int g, int q, float acc[4][4]) {
    unsigned ah[4], al[4];
    lda_bf(Ah, mw, g, q, ah);
    lda_bf(Al, mw, g, q, al);
#pragma unroll
    for (int j = 0; j < 4; j++) {
        unsigned bh[2], bl[2];
        if (BNN) { ldb_nn(Bh, nw + 8 * j, g, q, bh); ldb_nn(Bl, nw + 8 * j, g, q, bl); }
        else     { ldb_nt(Bh, nw + 8 * j, g, q, bh); ldb_nt(Bl, nw + 8 * j, g, q, bl); }
        mmabf(acc[j], ah, bh);
        mmabf(acc[j], ah, bl);
        mmabf(acc[j], al, bh);
    }
}

__device__ __forceinline__ void warp_bmma128(const unsigned* Ah, const unsigned* Al,
                                             const unsigned* Bh, const unsigned* Bl,
                                             int mw, int nw, int g, int q,
                                             float acc[2][4][4]) {
    unsigned ah0[4], al0[4], ah1[4], al1[4];
    lda_bf(Ah, mw, g, q, ah0);
    lda_bf(Al, mw, g, q, al0);
    lda_bf(Ah, mw + 64, g, q, ah1);
    lda_bf(Al, mw + 64, g, q, al1);
#pragma unroll
    for (int j = 0; j < 4; j++) {
        unsigned bh[2], bl[2];
        ldb_nt(Bh, nw + 8 * j, g, q, bh);
        ldb_nt(Bl, nw + 8 * j, g, q, bl);
        mmabf(acc[0][j], ah0, bh); mmabf(acc[0][j], ah0, bl); mmabf(acc[0][j], al0, bh);
        mmabf(acc[1][j], ah1, bh); mmabf(acc[1][j], ah1, bl); mmabf(acc[1][j], al1, bh);
    }
}

// ---------------- main loops (R9-proven single-buffer) ----------------
template<bool ADD2>
__device__ __forceinline__ void loop64_nt(const float* __restrict__ Az,
                                          const float* __restrict__ A2z, int ldA,
                                          const float* __restrict__ Bz, int ldB, int K,
                                          unsigned* Ah, unsigned* Al,
                                          unsigned* Bh, unsigned* Bl, float acc[4][4]) {
    int tid = threadIdx.x;
    int r_ = tid >> 2, q_ = tid & 3;
    int lane = tid & 31, g = lane >> 2, q = lane & 3;
    int warp = tid >> 5, mw = (warp & 3) * 16, nw = (warp >> 2) * 32;
    float4 ar = *(const float4*)&Az[(long)r_ * ldA + q_ * 4];
    float4 br = *(const float4*)&Bz[(long)r_ * ldB + q_ * 4];
    float4 a2 = make_float4(0.f, 0.f, 0.f, 0.f);
    if (ADD2) a2 = *(const float4*)&A2z[(long)r_ * ldA + q_ * 4];
    for (int k0 = 0; k0 < K; k0 += 16) {
        if (ADD2) { ar.x += a2.x; ar.y += a2.y; ar.z += a2.z; ar.w += a2.w; }
        uint2 h, l;
        bsplit4(ar, h, l);
        *(uint2*)&Ah[r_ * SKH + q_ * 2] = h;
        *(uint2*)&Al[r_ * SKH + q_ * 2] = l;
        bsplit4(br, h, l);
        *(uint2*)&Bh[r_ * SKH + q_ * 2] = h;
        *(uint2*)&Bl[r_ * SKH + q_ * 2] = l;
        __syncthreads();
        int kn = k0 + 16;
        if (kn < K) {
            ar = *(const float4*)&Az[(long)r_ * ldA + kn + q_ * 4];
            br = *(const float4*)&Bz[(long)r_ * ldB + kn + q_ * 4];
            if (ADD2) a2 = *(const float4*)&A2z[(long)r_ * ldA + kn + q_ * 4];
        }
        warp_bmma<false>(Ah, Al, Bh, Bl, mw, nw, g, q, acc);
        __syncthreads();
    }
}

__device__ __forceinline__ void loop64_nn(const float* __restrict__ Az, int ldA,
                                          const float* __restrict__ Bz, int ldB, int K,
                                          unsigned* Ah, unsigned* Al,
                                          unsigned* Bh, unsigned* Bl, float acc[4][4]) {
    int tid = threadIdx.x;
    int r_ = tid >> 2, q_ = tid & 3;
    int kh = tid >> 5, c2 = (tid & 31) * 2;
    int lane = tid & 31, g = lane >> 2, q = lane & 3;
    int warp = tid >> 5, mw = (warp & 3) * 16, nw = (warp >> 2) * 32;
    float4 ar = *(const float4*)&Az[(long)r_ * ldA + q_ * 4];
    float2 be = *(const float2*)&Bz[(long)(2 * kh) * ldB + c2];
    float2 bo = *(const float2*)&Bz[(long)(2 * kh + 1) * ldB + c2];
    for (int k0 = 0; k0 < K; k0 += 16) {
        uint2 h, l;
        bsplit4(ar, h, l);
        *(uint2*)&Ah[r_ * SKH + q_ * 2] = h;
        *(uint2*)&Al[r_ * SKH + q_ * 2] = l;
        unsigned h0, l0, h1, l1;
        bsplit2(be.x, bo.x, h0, l0);
        bsplit2(be.y, bo.y, h1, l1);
        *(uint2*)&Bh[kh * SBN + c2] = make_uint2(h0, h1);
        *(uint2*)&Bl[kh * SBN + c2] = make_uint2(l0, l1);
        __syncthreads();
        int kn = k0 + 16;
        if (kn < K) {
            ar = *(const float4*)&Az[(long)r_ * ldA + kn + q_ * 4];
            be = *(const float2*)&Bz[(long)(kn + 2 * kh) * ldB + c2];
            bo = *(const float2*)&Bz[(long)(kn + 2 * kh + 1) * ldB + c2];
        }
        warp_bmma<true>(Ah, Al, Bh, Bl, mw, nw, g, q, acc);
        __syncthreads();
    }
}

__device__ __forceinline__ void loop128_nt(const float* __restrict__ Az, int ldA,
                                           const float* __restrict__ Bz, int ldB, int K,
                                           unsigned* Ah, unsigned* Al,
                                           unsigned* Bh, unsigned* Bl, float acc[2][4][4]) {
    int tid = threadIdx.x;
    int r_ = tid >> 2, q_ = tid & 3;
    int lane = tid & 31, g = lane >> 2, q = lane & 3;
    int warp = tid >> 5, mw = (warp & 3) * 16, nw = (warp >> 2) * 32;
    int aoff = r_ * SKH + q_ * 2;
    int aoff2 = (r_ + 64) * SKH + q_ * 2;
    float4 a0 = *(const float4*)&Az[(long)r_ * ldA + q_ * 4];
    float4 a1 = *(const float4*)&Az[(long)(r_ + 64) * ldA + q_ * 4];
    float4 br = *(const float4*)&Bz[(long)r_ * ldB + q_ * 4];
    for (int k0 = 0; k0 < K; k0 += 16) {
        uint2 h, l;
        bsplit4(a0, h, l);
        *(uint2*)&Ah[aoff] = h; *(uint2*)&Al[aoff] = l;
        bsplit4(a1, h, l);
        *(uint2*)&Ah[aoff2] = h; *(uint2*)&Al[aoff2] = l;
        bsplit4(br, h, l);
        *(uint2*)&Bh[r_ * SKH + q_ * 2] = h; *(uint2*)&Bl[r_ * SKH + q_ * 2] = l;
        __syncthreads();
        int kn = k0 + 16;
        if (kn < K) {
            a0 = *(const float4*)&Az[(long)r_ * ldA + kn + q_ * 4];
            a1 = *(const float4*)&Az[(long)(r_ + 64) * ldA + kn + q_ * 4];
            br = *(const float4*)&Bz[(long)r_ * ldB + kn + q_ * 4];
        }
        warp_bmma128(Ah, Al, Bh, Bl, mw, nw, g, q, acc);
        __syncthreads();
    }
}

// ---------------- epilogues ----------------
__device__ __forceinline__ void epi_tile(float* C, int ldC, int row, int col,
                                         const float v[4], const float* bias,
                                         float alpha, bool prelu) {
    float b0 = 0.f, b1 = 0.f;
    if (bias) { b0 = bias[col]; b1 = bias[col + 1]; }
    float v00 = v[0] + b0, v01 = v[1] + b1, v10 = v[2] + b0, v11 = v[3] + b1;
    if (prelu) {
        v00 = (v00 >= 0.f) ? v00 : alpha * v00;
        v01 = (v01 >= 0.f) ? v01 : alpha * v01;
        v10 = (v10 >= 0.f) ? v10 : alpha * v10;
        v11 = (v11 >= 0.f) ? v11 : alpha * v11;
    }
    *(float2*)&C[(long)row * ldC + col]       = make_float2(v00, v01);
    *(float2*)&C[(long)(row + 8) * ldC + col] = make_float2(v10, v11);
}

__device__ __forceinline__ void epi64(float* C, int ldC, int m0, int n0,
                                      float acc[4][4], const float* bias,
                                      float alpha, bool prelu) {
    int tid = threadIdx.x, lane = tid & 31, g = lane >> 2, q = lane & 3;
    int warp = tid >> 5, mw = (warp & 3) * 16, nw = (warp >> 2) * 32;
    int row = m0 + mw + g;
#pragma unroll
    for (int j = 0; j < 4; j++)
        epi_tile(C, ldC, row, n0 + nw + 8 * j + 2 * q, acc[j], bias, alpha, prelu);
}

__device__ __forceinline__ void epi128(float* C, int ldC, int m0, int n0,
                                       float acc[2][4][4], const float* bias,
                                       float alpha, bool prelu) {
    int tid = threadIdx.x, lane = tid & 31, g = lane >> 2, q = lane & 3;
    int warp = tid >> 5, mw = (warp & 3) * 16, nw = (warp >> 2) * 32;
#pragma unroll
    for (int i = 0; i < 2; i++) {
        int row = m0 + mw + i * 64 + g;
#pragma unroll
        for (int j = 0; j < 4; j++)
            epi_tile(C, ldC, row, n0 + nw + 8 * j + 2 * q, acc[i][j], bias, alpha, prelu);
    }
}

// =============== generic NT 64x64 GEMM (fc / l2 / mlp1) ===============
template<bool ADD2>
__global__ void __launch_bounds__(256, 3) k_gemm64(
    const float* __restrict__ A, const float* __restrict__ A2,
    const float* __restrict__ B, const float* __restrict__ bias,
    float* __restrict__ C, int Nc, int K,
    long sAz, int ldA, long sBz, int ldB, int bMod, long sCz, int ldC,
    const float* __restrict__ alpha_ptr)
{
    __shared__ __align__(16) unsigned Ah[AS64], Al[AS64];
    __shared__ __align__(16) unsigned Bh[AS64], Bl[AS64];
    int z = blockIdx.z;
    int m0 = blockIdx.y * 64, n0 = blockIdx.x * 64;
    int wz = z % bMod;
    const float* Az = A + (long)z * sAz + (long)m0 * ldA;
    const float* Bz = B + (long)wz * sBz + (long)n0 * ldB;
    float* Cz = C + (long)z * sCz;

    float acc[4][4] = {};
    loop64_nt<ADD2>(Az, ADD2 ? (A2 + (long)z * sAz + (long)m0 * ldA) : nullptr, ldA,
                    Bz, ldB, K, Ah, Al, Bh, Bl, acc);
    float alpha = alpha_ptr ? *alpha_ptr : 0.f;
    epi64(Cz, ldC, m0, n0, acc, bias ? (bias + wz * Nc) : nullptr,
          alpha, alpha_ptr != nullptr);
}

// =============== feats: fused S, BOTH batches, split-K x2 (R9 exact) ===============
__global__ void __launch_bounds__(256, 3) k_feats(
    const float* __restrict__ Tm, const float* __restrict__ theta,
    const float* __restrict__ Ab, const float* __restrict__ H,
    float* __restrict__ P, int l)
{
    __shared__ __align__(16) unsigned A0h[AS64], A0l[AS64];
    __shared__ __align__(16) unsigned A1h[AS64], A1l[AS64];
    __shared__ __align__(16) unsigned B0h[BSNN], B0l[BSNN];
    __shared__ __align__(16) unsigned B1h[BSNN], B1l[BSNN];
    int z = blockIdx.z;
    int r = z % K_R, chunk = z / K_R;
    const float* T0 = Tm + (long)((l * K_R + r) * K_E) * NN1;
    const float* T1 = T0 + NN1;
    const float* T2 = T1 + NN1;
    const float* A0 = Ab + (long)r * NN1;
    const float* A1 = Ab + (long)(K_R + r) * NN1;
    const float* H0 = H + (long)r * NF1;
    const float* H1 = H + (long)(K_R + r) * NF1;
    float* C0 = P + (long)(chunk * (K_B * K_R) + r) * NF1;
    float* C1 = P + (long)(chunk * (K_B * K_R) + K_R + r) * NF1;
    float t0 = theta[(l * K_R + r) * K_E + 0];
    float t1 = theta[(l * K_R + r) * K_E + 1];
    float t2 = theta[(l * K_R + r) * K_E + 2];
    int m0 = blockIdx.y * 64;
    int Ks = chunk * (K_N / 2), Ke = Ks + K_N / 2;

    int tid = threadIdx.x;
    int r_ = tid >> 2, q_ = tid & 3;
    int kh = tid >> 5, c2 = (tid & 31) * 2;
    int lane = tid & 31, g = lane >> 2, q = lane & 3;
    int warp = tid >> 5, mw = (warp & 3) * 16, nw = (warp >> 2) * 32;

    float acc0[4][4] = {}, acc1[4][4] = {};

    float4 tv0, tv1, tv2, av0, av1;
    float2 h0e, h0o, h1e, h1o;
    {
        long off = (long)(m0 + r_) * K_N + Ks + q_ * 4;
        tv0 = *(const float4*)(T0 + off); tv1 = *(const float4*)(T1 + off);
        tv2 = *(const float4*)(T2 + off);
        av0 = *(const float4*)(A0 + off); av1 = *(const float4*)(A1 + off);
        h0e = *(const float2*)&H0[(long)(Ks + 2 * kh) * K_F + c2];
        h0o = *(const float2*)&H0[(long)(Ks + 2 * kh + 1) * K_F + c2];
        h1e = *(const float2*)&H1[(long)(Ks + 2 * kh) * K_F + c2];
        h1o = *(const float2*)&H1[(long)(Ks + 2 * kh + 1) * K_F + c2];
    }
    for (int k0 = Ks; k0 < Ke; k0 += 16) {
        float4 sv;
        sv.x = t0 * tv0.x + t1 * tv1.x + t2 * tv2.x;
        sv.y = t0 * tv0.y + t1 * tv1.y + t2 * tv2.y;
        sv.z = t0 * tv0.z + t1 * tv1.z + t2 * tv2.z;
        sv.w = t0 * tv0.w + t1 * tv1.w + t2 * tv2.w;
        float4 sa0 = make_float4(sv.x * av0.x, sv.y * av0.y, sv.z * av0.z, sv.w * av0.w);
        float4 sa1 = make_float4(sv.x * av1.x, sv.y * av1.y, sv.z * av1.z, sv.w * av1.w);
        uint2 h, l;
        bsplit4(sa0, h, l);
        *(uint2*)&A0h[r_ * SKH + q_ * 2] = h;
        *(uint2*)&A0l[r_ * SKH + q_ * 2] = l;
        bsplit4(sa1, h, l);
        *(uint2*)&A1h[r_ * SKH + q_ * 2] = h;
        *(uint2*)&A1l[r_ * SKH + q_ * 2] = l;
        unsigned hh0, ll0, hh1, ll1;
        bsplit2(h0e.x, h0o.x, hh0, ll0);
        bsplit2(h0e.y, h0o.y, hh1, ll1);
        *(uint2*)&B0h[kh * SBN + c2] = make_uint2(hh0, hh1);
        *(uint2*)&B0l[kh * SBN + c2] = make_uint2(ll0, ll1);
        bsplit2(h1e.x, h1o.x, hh0, ll0);
        bsplit2(h1e.y, h1o.y, hh1, ll1);
        *(uint2*)&B1h[kh * SBN + c2] = make_uint2(hh0, hh1);
        *(uint2*)&B1l[kh * SBN + c2] = make_uint2(ll0, ll1);
        __syncthreads();
        int kn = k0 + 16;
        if (kn < Ke) {
            long off = (long)(m0 + r_) * K_N + kn + q_ * 4;
            tv0 = *(const float4*)(T0 + off); tv1 = *(const float4*)(T1 + off);
            tv2 = *(const float4*)(T2 + off);
            av0 = *(const float4*)(A0 + off); av1 = *(const float4*)(A1 + off);
            h0e = *(const float2*)&H0[(long)(kn + 2 * kh) * K_F + c2];
            h0o = *(const float2*)&H0[(long)(kn + 2 * kh + 1) * K_F + c2];
            h1e = *(const float2*)&H1[(long)(kn + 2 * kh) * K_F + c2];
            h1o = *(const float2*)&H1[(long)(kn + 2 * kh + 1) * K_F + c2];
        }
        warp_bmma<true>(A0h, A0l, B0h, B0l, mw, nw, g, q, acc0);
        warp_bmma<true>(A1h, A1l, B1h, B1l, mw, nw, g, q, acc1);
        __syncthreads();
    }
    epi64(C0, K_F, m0, 0, acc0, nullptr, 0.f, false);
    epi64(C1, K_F, m0, 0, acc1, nullptr, 0.f, false);
}

// =============== fused q,k,v + ts projections, BM=128 (R9 exact) ===============
__global__ void __launch_bounds__(256, 2) k_qkv_ts(
    const float* __restrict__ h, const float* __restrict__ skip,
    const float* __restrict__ qw, const float* __restrict__ kw, const float* __restrict__ vw,
    const float* __restrict__ qb, const float* __restrict__ kb, const float* __restrict__ vb,
    const float* __restrict__ l1w, const float* __restrict__ l1b,
    float* __restrict__ q, float* __restrict__ k, float* __restrict__ v,
    float* __restrict__ cat)
{
    __shared__ __align__(16) unsigned Ah[AS128], Al[AS128];
    __shared__ __align__(16) unsigned Bh[AS64], Bl[AS64];
    int x = blockIdx.x;
    int m0 = blockIdx.y * 128;
    const float *A, *W, *bb;
    float* C; int ldC, n0;
    if (x < 12) {
        int which = x >> 2; n0 = (x & 3) * 64;
        A = h;
        W = ((which == 0) ? qw : (which == 1) ? kw : vw) + (long)n0 * K_INRET;
        bb = (which == 0) ? qb : (which == 1) ? kb : vb;
        C = (which == 0) ? q : (which == 1) ? k : v;
        ldC = K_INTER;
    } else {
        n0 = (x - 12) * 64;
        A = skip;
        W = l1w + (long)n0 * K_HRET;
        bb = l1b;
        C = cat + K_OUTRET;
        ldC = K_CAT;
    }
    float acc[2][4][4] = {};
    loop128_nt(A + (long)m0 * K_INRET, K_INRET, W, K_INRET, K_INRET,
               Ah, Al, Bh, Bl, acc);
    epi128(C, ldC, m0, n0, acc, bb, 0.f, false);
}

// =============== triangular masked scores, BM=64 (272 blocks, occ3) ===============
__global__ void __launch_bounds__(256, 3) k_scores(
    const float* __restrict__ q, const float* __restrict__ k, float* __restrict__ ms)
{
    __shared__ __align__(16) unsigned Ah[AS64], Al[AS64];
    __shared__ __align__(16) unsigned Bh[AS64], Bl[AS64];
    int i = blockIdx.x;
    int mt = (int)((sqrtf(8.f * i + 1.f) - 1.f) * 0.5f);
    while ((mt + 1) * (mt + 2) / 2 <= i) mt++;
    while (mt * (mt + 1) / 2 > i) mt--;
    int nt = i - mt * (mt + 1) / 2;
    int m0 = mt * 64, n0 = nt * 64;
    int z = blockIdx.y;
    const float* Az = q + (long)z * K_N * K_INTER + (long)m0 * K_INTER;
    const float* Bz = k + (long)z * K_N * K_INTER + (long)n0 * K_INTER;
    float* Cz = ms + (long)z * NN1;

    float acc[4][4] = {};
    loop64_nt<false>(Az, nullptr, K_INTER, Bz, K_INTER, K_INTER, Ah, Al, Bh, Bl, acc);

    int tid = threadIdx.x, lane = tid & 31, g = lane >> 2, qq = lane & 3;
    int warp = tid >> 5, mw = (warp & 3) * 16, nw = (warp >> 2) * 32;
    int row = m0 + mw + g;
#pragma unroll
    for (int j = 0; j < 4; j++) {
        int col = n0 + nw + 8 * j + 2 * qq;
        float v00 = (row > col)         ? INV_GAMMA * acc[j][0] : 0.f;
        float v01 = (row > col + 1)     ? INV_GAMMA * acc[j][1] : 0.f;
        float v10 = (row + 8 > col)     ? INV_GAMMA * acc[j][2] : 0.f;
        float v11 = (row + 8 > col + 1) ? INV_GAMMA * acc[j][3] : 0.f;
        *(float2*)&Cz[(long)row * K_N + col]       = make_float2(v00, v01);
        *(float2*)&Cz[(long)(row + 8) * K_N + col] = make_float2(v10, v11);
    }
}

// =============== ret = ms @ v, causal K-limit, NO split (128 blocks) ===============
__global__ void __launch_bounds__(256, 3) k_ret(
    const float* __restrict__ ms, const float* __restrict__ v, float* __restrict__ ret)
{
    __shared__ __align__(16) unsigned Ah[AS64], Al[AS64];
    __shared__ __align__(16) unsigned Bh[BSNN], Bl[BSNN];
    int b = blockIdx.z;
    int m0 = blockIdx.y * 64, n0 = blockIdx.x * 64;
    int Keff = m0 + 64;
    const float* Az = ms + (long)b * NN1 + (long)m0 * K_N;
    const float* Bz = v + (long)b * K_N * K_INTER + n0;
    float* Cz = ret + (long)b * K_N * K_OUTRET;

    float acc[4][4] = {};
    loop64_nn(Az, K_N, Bz, K_INTER, Keff, Ah, Al, Bh, Bl, acc);
    epi64(Cz, K_OUTRET, m0, n0, acc, nullptr, 0.f, false);
}

// =============== eta = PReLU(ret @ rw^T + rb) -> cat[:, :256] ===============
__global__ void __launch_bounds__(256, 3) k_eta(
    const float* __restrict__ ret, const float* __restrict__ rw,
    const float* __restrict__ rb, const float* __restrict__ a_ret,
    float* __restrict__ cat)
{
    __shared__ __align__(16) unsigned Ah[AS64], Al[AS64];
    __shared__ __align__(16) unsigned Bh[AS64], Bl[AS64];
    int n0 = blockIdx.x * 64, m0 = blockIdx.y * 64;
    float acc[4][4] = {};
    loop64_nt<false>(ret + (long)m0 * K_OUTRET, nullptr, K_OUTRET,
                     rw + (long)n0 * K_INTER, K_INTER, K_INTER,
                     Ah, Al, Bh, Bl, acc);
    epi64(cat, K_CAT, m0, n0, acc, rb, *a_ret, true);
}

// ---------------- conv over relations + PReLU ----------------
__global__ void k_conv(const float* __restrict__ diff, const float* __restrict__ cw,
                       const float* __restrict__ cb, const float* __restrict__ a1,
                       int l, float* __restrict__ u) {
    const int PQ = K_N * K_F / 4;
    int i = blockIdx.x * 256 + threadIdx.x;
    if (i >= K_B * K_R * PQ) return;
    int pq = i % PQ; int s = (i / PQ) % K_R; int b = i / (PQ * K_R);
    float bb = cb[l * K_R + s];
    float4 acc = make_float4(bb, bb, bb, bb);
    const float4* d4 = (const float4*)diff;
#pragma unroll
    for (int r2 = 0; r2 < K_R; r2++) {
        float w = cw[(l * K_R + s) * K_R + r2];
        float4 v = d4[(long)(b * K_R + r2) * PQ + pq];
        acc.x += w * v.x; acc.y += w * v.y; acc.z += w * v.z; acc.w += w * v.w;
    }
    float al = a1[l];
    acc.x = (acc.x >= 0.f) ? acc.x : al * acc.x;
    acc.y = (acc.y >= 0.f) ? acc.y : al * acc.y;
    acc.z = (acc.z >= 0.f) ? acc.z : al * acc.z;
    acc.w = (acc.w >= 0.f) ? acc.w : al * acc.w;
    ((float4*)u)[i] = acc;
}

// ---------------- initial skip transpose ----------------
__global__ void k_skip0(const float* __restrict__ x, float* __restrict__ sk) {
    int i = blockIdx.x * 256 + threadIdx.x;
    if (i >= K_B * K_N * K_R * K_F) return;
    int d = i % K_F;
    int r = (i / K_F) % K_R;
    int n = (i / (K_F * K_R)) % K_N;
    int b = i / (K_F * K_R * K_N);
    sk[i] = x[(((long)b * K_R + r) * K_N + n) * K_F + d];
}

// ---------------- final tiny GEMM: out[2048,2] ----------------
__global__ void k_mlp2(const float* __restrict__ m1, const float* __restrict__ w,
                       const float* __restrict__ b, float* __restrict__ out) {
    __shared__ float ws[2 * K_H1];
    int tid = threadIdx.x;
    if (tid < 2 * K_H1) ws[tid] = w[tid];
    __syncthreads();
    int row = blockIdx.x * 256 + tid;
    const float4* mr = (const float4*)(m1 + (long)row * K_H1);
    float s0 = 0.f, s1 = 0.f;
#pragma unroll
    for (int i = 0; i < K_H1 / 4; i++) {
        float4 v = mr[i];
        s0 += v.x * ws[i * 4] + v.y * ws[i * 4 + 1] + v.z * ws[i * 4 + 2] + v.w * ws[i * 4 + 3];
        s1 += v.x * ws[K_H1 + i * 4] + v.y * ws[K_H1 + i * 4 + 1]
            + v.z * ws[K_H1 + i * 4 + 2] + v.w * ws[K_H1 + i * 4 + 3];
    }
    out[(long)row * 2]     = s0 + b[0];
    out[(long)row * 2 + 1] = s1 + b[1];
}

// ---------------- host launcher ----------------
extern "C" void kernel_launch(void* const* d_in, const int* in_sizes, int n_in,
                              void* d_out, int out_size) {
    const float* x      = (const float*)d_in[0];
    const float* a      = (const float*)d_in[1];
    const float* T      = (const float*)d_in[2];
    const float* theta  = (const float*)d_in[3];
    const float* fc_w   = (const float*)d_in[4];
    const float* fc_b   = (const float*)d_in[5];
    const float* conv_w = (const float*)d_in[6];
    const float* conv_b = (const float*)d_in[7];
    const float* a0     = (const float*)d_in[8];
    const float* a1     = (const float*)d_in[9];
    const float* qw = (const float*)d_in[10]; const float* qb = (const float*)d_in[11];
    const float* kw = (const float*)d_in[12]; const float* kb = (const float*)d_in[13];
    const float* vw = (const float*)d_in[14]; const float* vb = (const float*)d_in[15];
    const float* rw = (const float*)d_in[16]; const float* rb = (const float*)d_in[17];
    const float* a_ret = (const float*)d_in[18];
    const float* l1w = (const float*)d_in[19]; const float* l1b = (const float*)d_in[20];
    const float* l2w = (const float*)d_in[21]; const float* l2b = (const float*)d_in[22];
    const float* m1w = (const float*)d_in[23]; const float* m1b = (const float*)d_in[24];
    const float* m2w = (const float*)d_in[25]; const float* m2b = (const float*)d_in[26];
    const float* a_mlp = (const float*)d_in[27];
    float* out = (float*)d_out;

    float *P, *diff, *h, *q, *k, *v, *ms, *cat, *skA, *skB, *m1;
    cudaGetSymbolAddress((void**)&P, g_P);
    cudaGetSymbolAddress((void**)&diff, g_diff);
    cudaGetSymbolAddress((void**)&h, g_h);
    cudaGetSymbolAddress((void**)&q, g_q);
    cudaGetSymbolAddress((void**)&k, g_k);
    cudaGetSymbolAddress((void**)&v, g_v);
    cudaGetSymbolAddress((void**)&ms, g_ms);
    cudaGetSymbolAddress((void**)&cat, g_cat);
    cudaGetSymbolAddress((void**)&skA, g_skipA);
    cudaGetSymbolAddress((void**)&skB, g_skipB);
    cudaGetSymbolAddress((void**)&m1, g_m1);

    const int M2 = K_B * K_N;  // 2048
    float* ret = P + (long)K_B * K_R * NF1;  // reuse upper half of P as ret buffer

    { int tot = K_B * K_N * K_R * K_F;
      k_skip0<<<(tot + 255) / 256, 256>>>(x, skA); }

    const float* hc = x;
    float* sin_ = skA;
    float* sout = skB;

    for (int l = 0; l < 2; l++) {
        k_feats<<<dim3(1, K_N / 64, K_B * K_R), 256>>>(T, theta, a, hc, P, l);

        k_gemm64<true><<<dim3(1, K_N / 64, K_B * K_R), 256>>>(
            P, P + (long)K_B * K_R * NF1,
            fc_w + (long)l * K_R * K_F * K_F, fc_b + (long)l * K_R * K_F, diff,
            K_F, K_F, NF1, K_F, (long)K_F * K_F, K_F, K_R, NF1, K_F, a0 + l);

        { int tot = K_B * K_R * K_N * K_F / 4;
          k_conv<<<(tot + 255) / 256, 256>>>(diff, conv_w, conv_b, a1, l, h); }
        hc = h;

        k_qkv_ts<<<dim3(14, K_N * K_B / 128), 256>>>(
            h, sin_,
            qw + (long)l * K_INTER * K_INRET, kw + (long)l * K_INTER * K_INRET,
            vw + (long)l * K_INTER * K_INRET,
            qb + (long)l * K_INTER, kb + (long)l * K_INTER, vb + (long)l * K_INTER,
            l1w + (long)l * K_H1 * K_HRET, l1b + (long)l * K_H1,
            q, k, v, cat);

        // triangular masked scores, BM=64 (272 blocks, occ3)
        k_scores<<<dim3(136, 2), 256>>>(q, k, ms);

        // ret = ms @ v, no split-K (128 blocks)
        k_ret<<<dim3(K_OUTRET / 64, K_N / 64, K_B), 256>>>(ms, v, ret);

        // eta single-stream (128 blocks)
        k_eta<<<dim3(K_OUTRET / 64, M2 / 64), 256>>>(
            ret, rw + (long)l * K_OUTRET * K_INTER, rb + (long)l * K_OUTRET,
            a_ret + l, cat);

        k_gemm64<false><<<dim3(K_HRET / 64, M2 / 64, 1), 256>>>(
            cat, nullptr, l2w + (long)l * K_HRET * K_CAT, l2b + (long)l * K_HRET, sout,
            K_HRET, K_CAT, 0, K_CAT, 0, K_CAT, 1, 0, K_HRET, nullptr);

        float* t0 = sin_; sin_ = sout; sout = t0;
    }

    k_gemm64<false><<<dim3(K_H1 / 64, M2 / 64, 1), 256>>>(
        sin_, nullptr, m1w, m1b, m1,
        K_H1, K_HRET, 0, K_HRET, 0, K_HRET, 1, 0, K_H1, a_mlp);
    k_mlp2<<<M2 / 256, 256>>>(m1, m2w, m2b, out);
}

// round 17
// speedup vs baseline: 1.2787x; 1.2322x over previous
#include <cuda_runtime.h>
#include <cuda_bf16.h>

#define K_B 2
#define K_R 5
#define K_N 1024
#define K_E 3
#define K_F 64
#define K_INRET 320
#define K_INTER 256
#define K_OUTRET 256
#define K_H1 128
#define K_HRET 320
#define K_CAT 384
#define INV_GAMMA 0.4f
#define SKH 12    // row-major bf16x2 tile stride (8 k-pairs + 4 pad)
#define SBN 72    // k-pair-major NN B tile stride
#define NN1 (K_N * K_N)
#define NF1 (K_N * K_F)
#define PHALF (2 * K_N * K_OUTRET)
#define AS64 (64 * SKH)
#define AS128 (128 * SKH)
#define BSNN (8 * SBN)

// ---------------- device scratch ----------------
__device__ __align__(16) float g_P[2 * K_B * K_R * K_N * K_F];
__device__ __align__(16) float g_diff [K_B * K_R * K_N * K_F];
__device__ __align__(16) float g_h    [K_B * K_R * K_N * K_F];
__device__ __align__(16) float g_q [K_B * K_N * K_INTER];
__device__ __align__(16) float g_k [K_B * K_N * K_INTER];
__device__ __align__(16) float g_v [K_B * K_N * K_INTER];
__device__ __align__(16) float g_ms [K_B * K_N * K_N];   // scores partial, K-chunk 0
__device__ __align__(16) float g_ms2[K_B * K_N * K_N];   // scores partial, K-chunk 1
__device__ __align__(16) float g_cat[K_B * K_N * K_CAT];
__device__ __align__(16) float g_skipA[K_B * K_N * K_HRET];
__device__ __align__(16) float g_skipB[K_B * K_N * K_HRET];
__device__ __align__(16) float g_m1[K_B * K_N * K_H1];

// ---------------- bf16 split helpers ----------------
__device__ __forceinline__ unsigned as_u(__nv_bfloat162 v) {
    return reinterpret_cast<unsigned&>(v);
}
__device__ __forceinline__ void bsplit4(float4 v, uint2& hi, uint2& lo) {
    __nv_bfloat162 h01 = __floats2bfloat162_rn(v.x, v.y);
    __nv_bfloat162 h23 = __floats2bfloat162_rn(v.z, v.w);
    float r0 = v.x - __bfloat162float(h01.x);
    float r1 = v.y - __bfloat162float(h01.y);
    float r2 = v.z - __bfloat162float(h23.x);
    float r3 = v.w - __bfloat162float(h23.y);
    __nv_bfloat162 l01 = __floats2bfloat162_rn(r0, r1);
    __nv_bfloat162 l23 = __floats2bfloat162_rn(r2, r3);
    hi = make_uint2(as_u(h01), as_u(h23));
    lo = make_uint2(as_u(l01), as_u(l23));
}
__device__ __forceinline__ void bsplit2(float a, float b, unsigned& hi, unsigned& lo) {
    __nv_bfloat162 h = __floats2bfloat162_rn(a, b);
    float ra = a - __bfloat162float(h.x);
    float rb = b - __bfloat162float(h.y);
    __nv_bfloat162 l = __floats2bfloat162_rn(ra, rb);
    hi = as_u(h); lo = as_u(l);
}

__device__ __forceinline__ void mmabf(float acc[4], const unsigned a[4], const unsigned b[2]) {
    asm volatile(
        "mma.sync.aligned.m16n8k16.row.col.f32.bf16.bf16.f32 "
        "{%0,%1,%2,%3}, {%4,%5,%6,%7}, {%8,%9}, {%0,%1,%2,%3};"
        : "+f"(acc[0]), "+f"(acc[1]), "+f"(acc[2]), "+f"(acc[3])
        : "r"(a[0]), "r"(a[1]), "r"(a[2]), "r"(a[3]), "r"(b[0]), "r"(b[1]));
}

__device__ __forceinline__ void lda_bf(const unsigned* A, int mrow, int g, int q,
                                       unsigned a[4]) {
    const unsigned* p = &A[(mrow + g) * SKH + q];
    a[0] = p[0];
    a[1] = p[8 * SKH];
    a[2] = p[4];
    a[3] = p[8 * SKH + 4];
}
__device__ __forceinline__ void ldb_nt(const unsigned* B, int nrow, int g, int q,
                                       unsigned b[2]) {
    const unsigned* p = &B[(nrow + g) * SKH + q];
    b[0] = p[0]; b[1] = p[4];
}
__device__ __forceinline__ void ldb_nn(const unsigned* B, int ncol, int g, int q,
                                       unsigned b[2]) {
    b[0] = B[q * SBN + ncol + g];
    b[1] = B[(q + 4) * SBN + ncol + g];
}

template<bool BNN>
__device__ __forceinline__ void warp_bmma(const unsigned* Ah, const unsigned* Al,
                                          const unsigned* Bh, const unsigned* Bl,
                                          int mw, int nw, int g, int q, float acc[4][4]) {
    unsigned ah[4], al[4];
    lda_bf(Ah, mw, g, q, ah);
    lda_bf(Al, mw, g, q, al);
#pragma unroll
    for (int j = 0; j < 4; j++) {
        unsigned bh[2], bl[2];
        if (BNN) { ldb_nn(Bh, nw + 8 * j, g, q, bh); ldb_nn(Bl, nw + 8 * j, g, q, bl); }
        else     { ldb_nt(Bh, nw + 8 * j, g, q, bh); ldb_nt(Bl, nw + 8 * j, g, q, bl); }
        mmabf(acc[j], ah, bh);
        mmabf(acc[j], ah, bl);
        mmabf(acc[j], al, bh);
    }
}

__device__ __forceinline__ void warp_bmma128(const unsigned* Ah, const unsigned* Al,
                                             const unsigned* Bh, const unsigned* Bl,
                                             int mw, int nw, int g, int q,
                                             float acc[2][4][4]) {
    unsigned ah0[4], al0[4], ah1[4], al1[4];
    lda_bf(Ah, mw, g, q, ah0);
    lda_bf(Al, mw, g, q, al0);
    lda_bf(Ah, mw + 64, g, q, ah1);
    lda_bf(Al, mw + 64, g, q, al1);
#pragma unroll
    for (int j = 0; j < 4; j++) {
        unsigned bh[2], bl[2];
        ldb_nt(Bh, nw + 8 * j, g, q, bh);
        ldb_nt(Bl, nw + 8 * j, g, q, bl);
        mmabf(acc[0][j], ah0, bh); mmabf(acc[0][j], ah0, bl); mmabf(acc[0][j], al0, bh);
        mmabf(acc[1][j], ah1, bh); mmabf(acc[1][j], ah1, bl); mmabf(acc[1][j], al1, bh);
    }
}

// ---------------- main loops (R9-proven single-buffer) ----------------
template<bool ADD2>
__device__ __forceinline__ void loop64_nt(const float* __restrict__ Az,
                                          const float* __restrict__ A2z, int ldA,
                                          const float* __restrict__ Bz, int ldB, int K,
                                          unsigned* Ah, unsigned* Al,
                                          unsigned* Bh, unsigned* Bl, float acc[4][4]) {
    int tid = threadIdx.x;
    int r_ = tid >> 2, q_ = tid & 3;
    int lane = tid & 31, g = lane >> 2, q = lane & 3;
    int warp = tid >> 5, mw = (warp & 3) * 16, nw = (warp >> 2) * 32;
    float4 ar = *(const float4*)&Az[(long)r_ * ldA + q_ * 4];
    float4 br = *(const float4*)&Bz[(long)r_ * ldB + q_ * 4];
    float4 a2 = make_float4(0.f, 0.f, 0.f, 0.f);
    if (ADD2) a2 = *(const float4*)&A2z[(long)r_ * ldA + q_ * 4];
    for (int k0 = 0; k0 < K; k0 += 16) {
        if (ADD2) { ar.x += a2.x; ar.y += a2.y; ar.z += a2.z; ar.w += a2.w; }
        uint2 h, l;
        bsplit4(ar, h, l);
        *(uint2*)&Ah[r_ * SKH + q_ * 2] = h;
        *(uint2*)&Al[r_ * SKH + q_ * 2] = l;
        bsplit4(br, h, l);
        *(uint2*)&Bh[r_ * SKH + q_ * 2] = h;
        *(uint2*)&Bl[r_ * SKH + q_ * 2] = l;
        __syncthreads();
        int kn = k0 + 16;
        if (kn < K) {
            ar = *(const float4*)&Az[(long)r_ * ldA + kn + q_ * 4];
            br = *(const float4*)&Bz[(long)r_ * ldB + kn + q_ * 4];
            if (ADD2) a2 = *(const float4*)&A2z[(long)r_ * ldA + kn + q_ * 4];
        }
        warp_bmma<false>(Ah, Al, Bh, Bl, mw, nw, g, q, acc);
        __syncthreads();
    }
}

// NN loop; ADD2 sums two A streams (ms partial planes) during staging.
template<bool ADD2>
__device__ __forceinline__ void loop64_nn(const float* __restrict__ Az,
                                          const float* __restrict__ A2z, int ldA,
                                          const float* __restrict__ Bz, int ldB, int K,
                                          unsigned* Ah, unsigned* Al,
                                          unsigned* Bh, unsigned* Bl, float acc[4][4]) {
    int tid = threadIdx.x;
    int r_ = tid >> 2, q_ = tid & 3;
    int kh = tid >> 5, c2 = (tid & 31) * 2;
    int lane = tid & 31, g = lane >> 2, q = lane & 3;
    int warp = tid >> 5, mw = (warp & 3) * 16, nw = (warp >> 2) * 32;
    float4 ar = *(const float4*)&Az[(long)r_ * ldA + q_ * 4];
    float4 a2 = make_float4(0.f, 0.f, 0.f, 0.f);
    if (ADD2) a2 = *(const float4*)&A2z[(long)r_ * ldA + q_ * 4];
    float2 be = *(const float2*)&Bz[(long)(2 * kh) * ldB + c2];
    float2 bo = *(const float2*)&Bz[(long)(2 * kh + 1) * ldB + c2];
    for (int k0 = 0; k0 < K; k0 += 16) {
        if (ADD2) { ar.x += a2.x; ar.y += a2.y; ar.z += a2.z; ar.w += a2.w; }
        uint2 h, l;
        bsplit4(ar, h, l);
        *(uint2*)&Ah[r_ * SKH + q_ * 2] = h;
        *(uint2*)&Al[r_ * SKH + q_ * 2] = l;
        unsigned h0, l0, h1, l1;
        bsplit2(be.x, bo.x, h0, l0);
        bsplit2(be.y, bo.y, h1, l1);
        *(uint2*)&Bh[kh * SBN + c2] = make_uint2(h0, h1);
        *(uint2*)&Bl[kh * SBN + c2] = make_uint2(l0, l1);
        __syncthreads();
        int kn = k0 + 16;
        if (kn < K) {
            ar = *(const float4*)&Az[(long)r_ * ldA + kn + q_ * 4];
            if (ADD2) a2 = *(const float4*)&A2z[(long)r_ * ldA + kn + q_ * 4];
            be = *(const float2*)&Bz[(long)(kn + 2 * kh) * ldB + c2];
            bo = *(const float2*)&Bz[(long)(kn + 2 * kh + 1) * ldB + c2];
        }
        warp_bmma<true>(Ah, Al, Bh, Bl, mw, nw, g, q, acc);
        __syncthreads();
    }
}

__device__ __forceinline__ void loop128_nt(const float* __restrict__ Az, int ldA,
                                           const float* __restrict__ Bz, int ldB, int K,
                                           unsigned* Ah, unsigned* Al,
                                           unsigned* Bh, unsigned* Bl, float acc[2][4][4]) {
    int tid = threadIdx.x;
    int r_ = tid >> 2, q_ = tid & 3;
    int lane = tid & 31, g = lane >> 2, q = lane & 3;
    int warp = tid >> 5, mw = (warp & 3) * 16, nw = (warp >> 2) * 32;
    int aoff = r_ * SKH + q_ * 2;
    int aoff2 = (r_ + 64) * SKH + q_ * 2;
    float4 a0 = *(const float4*)&Az[(long)r_ * ldA + q_ * 4];
    float4 a1 = *(const float4*)&Az[(long)(r_ + 64) * ldA + q_ * 4];
    float4 br = *(const float4*)&Bz[(long)r_ * ldB + q_ * 4];
    for (int k0 = 0; k0 < K; k0 += 16) {
        uint2 h, l;
        bsplit4(a0, h, l);
        *(uint2*)&Ah[aoff] = h; *(uint2*)&Al[aoff] = l;
        bsplit4(a1, h, l);
        *(uint2*)&Ah[aoff2] = h; *(uint2*)&Al[aoff2] = l;
        bsplit4(br, h, l);
        *(uint2*)&Bh[r_ * SKH + q_ * 2] = h; *(uint2*)&Bl[r_ * SKH + q_ * 2] = l;
        __syncthreads();
        int kn = k0 + 16;
        if (kn < K) {
            a0 = *(const float4*)&Az[(long)r_ * ldA + kn + q_ * 4];
            a1 = *(const float4*)&Az[(long)(r_ + 64) * ldA + kn + q_ * 4];
            br = *(const float4*)&Bz[(long)r_ * ldB + kn + q_ * 4];
        }
        warp_bmma128(Ah, Al, Bh, Bl, mw, nw, g, q, acc);
        __syncthreads();
    }
}

// ---------------- epilogues ----------------
__device__ __forceinline__ void epi_tile(float* C, int ldC, int row, int col,
                                         const float v[4], const float* bias,
                                         float alpha, bool prelu) {
    float b0 = 0.f, b1 = 0.f;
    if (bias) { b0 = bias[col]; b1 = bias[col + 1]; }
    float v00 = v[0] + b0, v01 = v[1] + b1, v10 = v[2] + b0, v11 = v[3] + b1;
    if (prelu) {
        v00 = (v00 >= 0.f) ? v00 : alpha * v00;
        v01 = (v01 >= 0.f) ? v01 : alpha * v01;
        v10 = (v10 >= 0.f) ? v10 : alpha * v10;
        v11 = (v11 >= 0.f) ? v11 : alpha * v11;
    }
    *(float2*)&C[(long)row * ldC + col]       = make_float2(v00, v01);
    *(float2*)&C[(long)(row + 8) * ldC + col] = make_float2(v10, v11);
}

__device__ __forceinline__ void epi64(float* C, int ldC, int m0, int n0,
                                      float acc[4][4], const float* bias,
                                      float alpha, bool prelu) {
    int tid = threadIdx.x, lane = tid & 31, g = lane >> 2, q = lane & 3;
    int warp = tid >> 5, mw = (warp & 3) * 16, nw = (warp >> 2) * 32;
    int row = m0 + mw + g;
#pragma unroll
    for (int j = 0; j < 4; j++)
        epi_tile(C, ldC, row, n0 + nw + 8 * j + 2 * q, acc[j], bias, alpha, prelu);
}

__device__ __forceinline__ void epi128(float* C, int ldC, int m0, int n0,
                                       float acc[2][4][4], const float* bias,
                                       float alpha, bool prelu) {
    int tid = threadIdx.x, lane = tid & 31, g = lane >> 2, q = lane & 3;
    int warp = tid >> 5, mw = (warp & 3) * 16, nw = (warp >> 2) * 32;
#pragma unroll
    for (int i = 0; i < 2; i++) {
        int row = m0 + mw + i * 64 + g;
#pragma unroll
        for (int j = 0; j < 4; j++)
            epi_tile(C, ldC, row, n0 + nw + 8 * j + 2 * q, acc[i][j], bias, alpha, prelu);
    }
}

// =============== generic NT 64x64 GEMM (fc / l2 / mlp1) ===============
template<bool ADD2>
__global__ void __launch_bounds__(256, 3) k_gemm64(
    const float* __restrict__ A, const float* __restrict__ A2,
    const float* __restrict__ B, const float* __restrict__ bias,
    float* __restrict__ C, int Nc, int K,
    long sAz, int ldA, long sBz, int ldB, int bMod, long sCz, int ldC,
    const float* __restrict__ alpha_ptr)
{
    __shared__ __align__(16) unsigned Ah[AS64], Al[AS64];
    __shared__ __align__(16) unsigned Bh[AS64], Bl[AS64];
    int z = blockIdx.z;
    int m0 = blockIdx.y * 64, n0 = blockIdx.x * 64;
    int wz = z % bMod;
    const float* Az = A + (long)z * sAz + (long)m0 * ldA;
    const float* Bz = B + (long)wz * sBz + (long)n0 * ldB;
    float* Cz = C + (long)z * sCz;

    float acc[4][4] = {};
    loop64_nt<ADD2>(Az, ADD2 ? (A2 + (long)z * sAz + (long)m0 * ldA) : nullptr, ldA,
                    Bz, ldB, K, Ah, Al, Bh, Bl, acc);
    float alpha = alpha_ptr ? *alpha_ptr : 0.f;
    epi64(Cz, ldC, m0, n0, acc, bias ? (bias + wz * Nc) : nullptr,
          alpha, alpha_ptr != nullptr);
}

// =============== feats: fused S, BOTH batches, split-K x2 (R9 exact) ===============
__global__ void __launch_bounds__(256, 2) k_feats(
    const float* __restrict__ Tm, const float* __restrict__ theta,
    const float* __restrict__ Ab, const float* __restrict__ H,
    float* __restrict__ P, int l)
{
    __shared__ __align__(16) unsigned A0h[AS64], A0l[AS64];
    __shared__ __align__(16) unsigned A1h[AS64], A1l[AS64];
    __shared__ __align__(16) unsigned B0h[BSNN], B0l[BSNN];
    __shared__ __align__(16) unsigned B1h[BSNN], B1l[BSNN];
    int z = blockIdx.z;
    int r = z % K_R, chunk = z / K_R;
    const float* T0 = Tm + (long)((l * K_R + r) * K_E) * NN1;
    const float* T1 = T0 + NN1;
    const float* T2 = T1 + NN1;
    const float* A0 = Ab + (long)r * NN1;
    const float* A1 = Ab + (long)(K_R + r) * NN1;
    const float* H0 = H + (long)r * NF1;
    const float* H1 = H + (long)(K_R + r) * NF1;
    float* C0 = P + (long)(chunk * (K_B * K_R) + r) * NF1;
    float* C1 = P + (long)(chunk * (K_B * K_R) + K_R + r) * NF1;
    float t0 = theta[(l * K_R + r) * K_E + 0];
    float t1 = theta[(l * K_R + r) * K_E + 1];
    float t2 = theta[(l * K_R + r) * K_E + 2];
    int m0 = blockIdx.y * 64;
    int Ks = chunk * (K_N / 2), Ke = Ks + K_N / 2;

    int tid = threadIdx.x;
    int r_ = tid >> 2, q_ = tid & 3;
    int kh = tid >> 5, c2 = (tid & 31) * 2;
    int lane = tid & 31, g = lane >> 2, q = lane & 3;
    int warp = tid >> 5, mw = (warp & 3) * 16, nw = (warp >> 2) * 32;

    float acc0[4][4] = {}, acc1[4][4] = {};

    float4 tv0, tv1, tv2, av0, av1;
    float2 h0e, h0o, h1e, h1o;
    {
        long off = (long)(m0 + r_) * K_N + Ks + q_ * 4;
        tv0 = *(const float4*)(T0 + off); tv1 = *(const float4*)(T1 + off);
        tv2 = *(const float4*)(T2 + off);
        av0 = *(const float4*)(A0 + off); av1 = *(const float4*)(A1 + off);
        h0e = *(const float2*)&H0[(long)(Ks + 2 * kh) * K_F + c2];
        h0o = *(const float2*)&H0[(long)(Ks + 2 * kh + 1) * K_F + c2];
        h1e = *(const float2*)&H1[(long)(Ks + 2 * kh) * K_F + c2];
        h1o = *(const float2*)&H1[(long)(Ks + 2 * kh + 1) * K_F + c2];
    }
    for (int k0 = Ks; k0 < Ke; k0 += 16) {
        float4 sv;
        sv.x = t0 * tv0.x + t1 * tv1.x + t2 * tv2.x;
        sv.y = t0 * tv0.y + t1 * tv1.y + t2 * tv2.y;
        sv.z = t0 * tv0.z + t1 * tv1.z + t2 * tv2.z;
        sv.w = t0 * tv0.w + t1 * tv1.w + t2 * tv2.w;
        float4 sa0 = make_float4(sv.x * av0.x, sv.y * av0.y, sv.z * av0.z, sv.w * av0.w);
        float4 sa1 = make_float4(sv.x * av1.x, sv.y * av1.y, sv.z * av1.z, sv.w * av1.w);
        uint2 h, l;
        bsplit4(sa0, h, l);
        *(uint2*)&A0h[r_ * SKH + q_ * 2] = h;
        *(uint2*)&A0l[r_ * SKH + q_ * 2] = l;
        bsplit4(sa1, h, l);
        *(uint2*)&A1h[r_ * SKH + q_ * 2] = h;
        *(uint2*)&A1l[r_ * SKH + q_ * 2] = l;
        unsigned hh0, ll0, hh1, ll1;
        bsplit2(h0e.x, h0o.x, hh0, ll0);
        bsplit2(h0e.y, h0o.y, hh1, ll1);
        *(uint2*)&B0h[kh * SBN + c2] = make_uint2(hh0, hh1);
        *(uint2*)&B0l[kh * SBN + c2] = make_uint2(ll0, ll1);
        bsplit2(h1e.x, h1o.x, hh0, ll0);
        bsplit2(h1e.y, h1o.y, hh1, ll1);
        *(uint2*)&B1h[kh * SBN + c2] = make_uint2(hh0, hh1);
        *(uint2*)&B1l[kh * SBN + c2] = make_uint2(ll0, ll1);
        __syncthreads();
        int kn = k0 + 16;
        if (kn < Ke) {
            long off = (long)(m0 + r_) * K_N + kn + q_ * 4;
            tv0 = *(const float4*)(T0 + off); tv1 = *(const float4*)(T1 + off);
            tv2 = *(const float4*)(T2 + off);
            av0 = *(const float4*)(A0 + off); av1 = *(const float4*)(A1 + off);
            h0e = *(const float2*)&H0[(long)(kn + 2 * kh) * K_F + c2];
            h0o = *(const float2*)&H0[(long)(kn + 2 * kh + 1) * K_F + c2];
            h1e = *(const float2*)&H1[(long)(kn + 2 * kh) * K_F + c2];
            h1o = *(const float2*)&H1[(long)(kn + 2 * kh + 1) * K_F + c2];
        }
        warp_bmma<true>(A0h, A0l, B0h, B0l, mw, nw, g, q, acc0);
        warp_bmma<true>(A1h, A1l, B1h, B1l, mw, nw, g, q, acc1);
        __syncthreads();
    }
    epi64(C0, K_F, m0, 0, acc0, nullptr, 0.f, false);
    epi64(C1, K_F, m0, 0, acc1, nullptr, 0.f, false);
}

// =============== fused q,k,v + ts projections, BM=128 (R9 exact) ===============
__global__ void __launch_bounds__(256, 2) k_qkv_ts(
    const float* __restrict__ h, const float* __restrict__ skip,
    const float* __restrict__ qw, const float* __restrict__ kw, const float* __restrict__ vw,
    const float* __restrict__ qb, const float* __restrict__ kb, const float* __restrict__ vb,
    const float* __restrict__ l1w, const float* __restrict__ l1b,
    float* __restrict__ q, float* __restrict__ k, float* __restrict__ v,
    float* __restrict__ cat)
{
    __shared__ __align__(16) unsigned Ah[AS128], Al[AS128];
    __shared__ __align__(16) unsigned Bh[AS64], Bl[AS64];
    int x = blockIdx.x;
    int m0 = blockIdx.y * 128;
    const float *A, *W, *bb;
    float* C; int ldC, n0;
    if (x < 12) {
        int which = x >> 2; n0 = (x & 3) * 64;
        A = h;
        W = ((which == 0) ? qw : (which == 1) ? kw : vw) + (long)n0 * K_INRET;
        bb = (which == 0) ? qb : (which == 1) ? kb : vb;
        C = (which == 0) ? q : (which == 1) ? k : v;
        ldC = K_INTER;
    } else {
        n0 = (x - 12) * 64;
        A = skip;
        W = l1w + (long)n0 * K_HRET;
        bb = l1b;
        C = cat + K_OUTRET;
        ldC = K_CAT;
    }
    float acc[2][4][4] = {};
    loop128_nt(A + (long)m0 * K_INRET, K_INRET, W, K_INRET, K_INRET,
               Ah, Al, Bh, Bl, acc);
    epi128(C, ldC, m0, n0, acc, bb, 0.f, false);
}

// =============== triangular masked scores, BM=128, split-K x2 -> 2 planes ===============
// grid (72, 2, 2): x = tri tile, y = batch, z = K chunk (0: k<128, 1: k>=128).
__global__ void __launch_bounds__(256, 2) k_scores(
    const float* __restrict__ q, const float* __restrict__ k,
    float* __restrict__ ms0, float* __restrict__ ms1)
{
    __shared__ __align__(16) unsigned Ah[AS128], Al[AS128];
    __shared__ __align__(16) unsigned Bh[AS64], Bl[AS64];
    int i = blockIdx.x;
    int mt = (int)((sqrtf(4.f * i + 1.f) - 1.f) * 0.5f);
    while (mt * mt + mt > i) mt--;
    while ((mt + 1) * (mt + 1) + (mt + 1) <= i) mt++;
    int nt = i - mt * mt - mt;
    int m0 = mt * 128, n0 = nt * 64;
    int z = blockIdx.y;
    int chunk = blockIdx.z;
    int kOff = chunk * (K_INTER / 2);
    const float* Az = q + (long)z * K_N * K_INTER + (long)m0 * K_INTER + kOff;
    const float* Bz = k + (long)z * K_N * K_INTER + (long)n0 * K_INTER + kOff;
    float* Cz = (chunk ? ms1 : ms0) + (long)z * NN1;

    float acc[2][4][4] = {};
    loop128_nt(Az, K_INTER, Bz, K_INTER, K_INTER / 2, Ah, Al, Bh, Bl, acc);

    int tid = threadIdx.x, lane = tid & 31, g = lane >> 2, qq = lane & 3;
    int warp = tid >> 5, mw = (warp & 3) * 16, nw = (warp >> 2) * 32;
#pragma unroll
    for (int i2 = 0; i2 < 2; i2++) {
        int row = m0 + mw + i2 * 64 + g;
#pragma unroll
        for (int j = 0; j < 4; j++) {
            int col = n0 + nw + 8 * j + 2 * qq;
            float v00 = (row > col)         ? INV_GAMMA * acc[i2][j][0] : 0.f;
            float v01 = (row > col + 1)     ? INV_GAMMA * acc[i2][j][1] : 0.f;
            float v10 = (row + 8 > col)     ? INV_GAMMA * acc[i2][j][2] : 0.f;
            float v11 = (row + 8 > col + 1) ? INV_GAMMA * acc[i2][j][3] : 0.f;
            *(float2*)&Cz[(long)row * K_N + col]       = make_float2(v00, v01);
            *(float2*)&Cz[(long)(row + 8) * K_N + col] = make_float2(v10, v11);
        }
    }
}

// =============== ret = (ms0+ms1) @ v, causal K-limit, split-K x2 (R9 structure) ===============
__global__ void __launch_bounds__(256, 3) k_ret(
    const float* __restrict__ ms0, const float* __restrict__ ms1,
    const float* __restrict__ v, float* __restrict__ P)
{
    __shared__ __align__(16) unsigned Ah[AS64], Al[AS64];
    __shared__ __align__(16) unsigned Bh[BSNN], Bl[BSNN];
    int z = blockIdx.z;
    int b = z & 1, chunk = z >> 1;
    int m0 = blockIdx.y * 64, n0 = blockIdx.x * 64;
    int Keff = m0 + 64;
    int half = Keff >> 1;
    int Ks = chunk ? half : 0;
    int Ke = chunk ? Keff : half;
    long aoff = (long)b * NN1 + (long)m0 * K_N + Ks;
    const float* Az  = ms0 + aoff;
    const float* A2z = ms1 + aoff;
    const float* Bz = v + (long)b * K_N * K_INTER + (long)Ks * K_INTER + n0;
    float* Cz = P + (long)chunk * PHALF + (long)b * K_N * K_OUTRET;

    float acc[4][4] = {};
    loop64_nn<true>(Az, A2z, K_N, Bz, K_INTER, Ke - Ks, Ah, Al, Bh, Bl, acc);
    epi64(Cz, K_OUTRET, m0, n0, acc, nullptr, 0.f, false);
}

// =============== eta = PReLU((P0+P1) @ rw^T + rb) -> cat (R9 exact) ===============
__global__ void __launch_bounds__(256, 3) k_eta(
    const float* __restrict__ P, const float* __restrict__ rw,
    const float* __restrict__ rb, const float* __restrict__ a_ret,
    float* __restrict__ cat)
{
    __shared__ __align__(16) unsigned Ah[AS64], Al[AS64];
    __shared__ __align__(16) unsigned Bh[AS64], Bl[AS64];
    int n0 = blockIdx.x * 64, m0 = blockIdx.y * 64;
    float acc[4][4] = {};
    loop64_nt<true>(P + (long)m0 * K_OUTRET, P + PHALF + (long)m0 * K_OUTRET, K_OUTRET,
                    rw + (long)n0 * K_INTER, K_INTER, K_INTER,
                    Ah, Al, Bh, Bl, acc);
    epi64(cat, K_CAT, m0, n0, acc, rb, *a_ret, true);
}

// ---------------- conv over relations + PReLU ----------------
__global__ void k_conv(const float* __restrict__ diff, const float* __restrict__ cw,
                       const float* __restrict__ cb, const float* __restrict__ a1,
                       int l, float* __restrict__ u) {
    const int PQ = K_N * K_F / 4;
    int i = blockIdx.x * 256 + threadIdx.x;
    if (i >= K_B * K_R * PQ) return;
    int pq = i % PQ; int s = (i / PQ) % K_R; int b = i / (PQ * K_R);
    float bb = cb[l * K_R + s];
    float4 acc = make_float4(bb, bb, bb, bb);
    const float4* d4 = (const float4*)diff;
#pragma unroll
    for (int r2 = 0; r2 < K_R; r2++) {
        float w = cw[(l * K_R + s) * K_R + r2];
        float4 v = d4[(long)(b * K_R + r2) * PQ + pq];
        acc.x += w * v.x; acc.y += w * v.y; acc.z += w * v.z; acc.w += w * v.w;
    }
    float al = a1[l];
    acc.x = (acc.x >= 0.f) ? acc.x : al * acc.x;
    acc.y = (acc.y >= 0.f) ? acc.y : al * acc.y;
    acc.z = (acc.z >= 0.f) ? acc.z : al * acc.z;
    acc.w = (acc.w >= 0.f) ? acc.w : al * acc.w;
    ((float4*)u)[i] = acc;
}

// ---------------- initial skip transpose ----------------
__global__ void k_skip0(const float* __restrict__ x, float* __restrict__ sk) {
    int i = blockIdx.x * 256 + threadIdx.x;
    if (i >= K_B * K_N * K_R * K_F) return;
    int d = i % K_F;
    int r = (i / K_F) % K_R;
    int n = (i / (K_F * K_R)) % K_N;
    int b = i / (K_F * K_R * K_N);
    sk[i] = x[(((long)b * K_R + r) * K_N + n) * K_F + d];
}

// ---------------- final tiny GEMM: out[2048,2] ----------------
__global__ void k_mlp2(const float* __restrict__ m1, const float* __restrict__ w,
                       const float* __restrict__ b, float* __restrict__ out) {
    __shared__ float ws[2 * K_H1];
    int tid = threadIdx.x;
    if (tid < 2 * K_H1) ws[tid] = w[tid];
    __syncthreads();
    int row = blockIdx.x * 256 + tid;
    const float4* mr = (const float4*)(m1 + (long)row * K_H1);
    float s0 = 0.f, s1 = 0.f;
#pragma unroll
    for (int i = 0; i < K_H1 / 4; i++) {
        float4 v = mr[i];
        s0 += v.x * ws[i * 4] + v.y * ws[i * 4 + 1] + v.z * ws[i * 4 + 2] + v.w * ws[i * 4 + 3];
        s1 += v.x * ws[K_H1 + i * 4] + v.y * ws[K_H1 + i * 4 + 1]
            + v.z * ws[K_H1 + i * 4 + 2] + v.w * ws[K_H1 + i * 4 + 3];
    }
    out[(long)row * 2]     = s0 + b[0];
    out[(long)row * 2 + 1] = s1 + b[1];
}

// ---------------- host launcher ----------------
extern "C" void kernel_launch(void* const* d_in, const int* in_sizes, int n_in,
                              void* d_out, int out_size) {
    const float* x      = (const float*)d_in[0];
    const float* a      = (const float*)d_in[1];
    const float* T      = (const float*)d_in[2];
    const float* theta  = (const float*)d_in[3];
    const float* fc_w   = (const float*)d_in[4];
    const float* fc_b   = (const float*)d_in[5];
    const float* conv_w = (const float*)d_in[6];
    const float* conv_b = (const float*)d_in[7];
    const float* a0     = (const float*)d_in[8];
    const float* a1     = (const float*)d_in[9];
    const float* qw = (const float*)d_in[10]; const float* qb = (const float*)d_in[11];
    const float* kw = (const float*)d_in[12]; const float* kb = (const float*)d_in[13];
    const float* vw = (const float*)d_in[14]; const float* vb = (const float*)d_in[15];
    const float* rw = (const float*)d_in[16]; const float* rb = (const float*)d_in[17];
    const float* a_ret = (const float*)d_in[18];
    const float* l1w = (const float*)d_in[19]; const float* l1b = (const float*)d_in[20];
    const float* l2w = (const float*)d_in[21]; const float* l2b = (const float*)d_in[22];
    const float* m1w = (const float*)d_in[23]; const float* m1b = (const float*)d_in[24];
    const float* m2w = (const float*)d_in[25]; const float* m2b = (const float*)d_in[26];
    const float* a_mlp = (const float*)d_in[27];
    float* out = (float*)d_out;

    float *P, *diff, *h, *q, *k, *v, *ms0, *ms1, *cat, *skA, *skB, *m1;
    cudaGetSymbolAddress((void**)&P, g_P);
    cudaGetSymbolAddress((void**)&diff, g_diff);
    cudaGetSymbolAddress((void**)&h, g_h);
    cudaGetSymbolAddress((void**)&q, g_q);
    cudaGetSymbolAddress((void**)&k, g_k);
    cudaGetSymbolAddress((void**)&v, g_v);
    cudaGetSymbolAddress((void**)&ms0, g_ms);
    cudaGetSymbolAddress((void**)&ms1, g_ms2);
    cudaGetSymbolAddress((void**)&cat, g_cat);
    cudaGetSymbolAddress((void**)&skA, g_skipA);
    cudaGetSymbolAddress((void**)&skB, g_skipB);
    cudaGetSymbolAddress((void**)&m1, g_m1);

    const int M2 = K_B * K_N;  // 2048

    { int tot = K_B * K_N * K_R * K_F;
      k_skip0<<<(tot + 255) / 256, 256>>>(x, skA); }

    const float* hc = x;
    float* sin_ = skA;
    float* sout = skB;

    for (int l = 0; l < 2; l++) {
        k_feats<<<dim3(1, K_N / 64, K_B * K_R), 256>>>(T, theta, a, hc, P, l);

        k_gemm64<true><<<dim3(1, K_N / 64, K_B * K_R), 256>>>(
            P, P + (long)K_B * K_R * NF1,
            fc_w + (long)l * K_R * K_F * K_F, fc_b + (long)l * K_R * K_F, diff,
            K_F, K_F, NF1, K_F, (long)K_F * K_F, K_F, K_R, NF1, K_F, a0 + l);

        { int tot = K_B * K_R * K_N * K_F / 4;
          k_conv<<<(tot + 255) / 256, 256>>>(diff, conv_w, conv_b, a1, l, h); }
        hc = h;

        k_qkv_ts<<<dim3(14, K_N * K_B / 128), 256>>>(
            h, sin_,
            qw + (long)l * K_INTER * K_INRET, kw + (long)l * K_INTER * K_INRET,
            vw + (long)l * K_INTER * K_INRET,
            qb + (long)l * K_INTER, kb + (long)l * K_INTER, vb + (long)l * K_INTER,
            l1w + (long)l * K_H1 * K_HRET, l1b + (long)l * K_H1,
            q, k, v, cat);

        // scores split-K x2 -> two masked partial planes (288 blocks)
        k_scores<<<dim3(72, 2, 2), 256>>>(q, k, ms0, ms1);

        // ret = (ms0+ms1) @ v, split-K x2 -> partials in P (256 blocks)
        k_ret<<<dim3(K_OUTRET / 64, K_N / 64, 4), 256>>>(ms0, ms1, v, P);

        // eta with fused partial reduce (128 blocks)
        k_eta<<<dim3(K_OUTRET / 64, M2 / 64), 256>>>(
            P, rw + (long)l * K_OUTRET * K_INTER, rb + (long)l * K_OUTRET,
            a_ret + l, cat);

        k_gemm64<false><<<dim3(K_HRET / 64, M2 / 64, 1), 256>>>(
            cat, nullptr, l2w + (long)l * K_HRET * K_CAT, l2b + (long)l * K_HRET, sout,
            K_HRET, K_CAT, 0, K_CAT, 0, K_CAT, 1, 0, K_HRET, nullptr);

        float* t0 = sin_; sin_ = sout; sout = t0;
    }

    k_gemm64<false><<<dim3(K_H1 / 64, M2 / 64, 1), 256>>>(
        sin_, nullptr, m1w, m1b, m1,
        K_H1, K_HRET, 0, K_HRET, 0, K_HRET, 1, 0, K_H1, a_mlp);
    k_mlp2<<<M2 / 256, 256>>>(m1, m2w, m2b, out);
}